// round 11
// baseline (speedup 1.0000x reference)
#include <cuda_runtime.h>
#include <math.h>
#include <mma.h>

using namespace nvcuda;

// Problem constants
#define B_    256
#define P_    100
#define ENC_  1536
#define DEC_  512
#define ATT_  256
#define EMB_  256
#define V_    193
#define T_    150
#define T1_   151
#define N1_   1792   // att2(256) + f_beta(1536)
#define K2_   2048   // awe(1536) + h(512)
#define N2_   2048   // 4*DEC gate-interleaved

#define HP_BLOCKS 112          // hproj tiles in fused kernel 1
#define HPP_GRID (HP_BLOCKS + B_)

// Scratch (device globals: allocation-free per harness rules)
__device__ float g_h[B_ * DEC_];
__device__ float g_c[B_ * DEC_];
__device__ float g_mean[B_ * ENC_];
__device__ float g_att1[B_ * P_ * ATT_];
__device__ float g_hproj[B_ * N1_];
__device__ float g_x[B_ * K2_];          // [gated awe (1536) | h (512)]
__device__ float g_Wcat1[DEC_ * N1_];    // [W_dec_att | W_f_beta]
__device__ float g_bcat1[N1_];
__device__ float g_Wcat2[K2_ * N2_];     // rows: [W_ih_enc ; W_hh], cols interleaved d*4+g
__device__ float g_embW[V_ * N2_];       // emb@W_ih_emb + b_ih + b_hh, cols interleaved

__device__ __forceinline__ float sigmoidf_(float x) { return 1.0f / (1.0f + expf(-x)); }

__device__ __forceinline__ float tf32r(float x) {
    unsigned int u = __float_as_uint(x), v;
    asm("cvt.rna.tf32.f32 %0, %1;" : "=r"(v) : "r"(u));
    return __uint_as_float(v);
}
__device__ __forceinline__ float4 tf32r4(float4 v) {
    return make_float4(tf32r(v.x), tf32r(v.y), tf32r(v.z), tf32r(v.w));
}

typedef wmma::fragment<wmma::matrix_a, 16, 16, 8, wmma::precision::tf32, wmma::row_major> FragA;
typedef wmma::fragment<wmma::matrix_b, 16, 16, 8, wmma::precision::tf32, wmma::row_major> FragB;
typedef wmma::fragment<wmma::accumulator, 16, 16, 8, float> FragC;

// ---------------------------------------------------------------------------
// Double-buffered tf32 tensor-core 32x128 GEMM tile, BK=32, 256 threads =
// 8 warps (2 M x 4 N). One __syncthreads per k0; next-tile stores overlap
// current-tile fragment loads + MMA.
// ---------------------------------------------------------------------------
__device__ __forceinline__ void gemm_tc_tile(const float* __restrict__ A, int lda,
                                             const float* __restrict__ W, int N, int K,
                                             int rows0, int cols0,
                                             float (*As)[32][36], float (*Bs)[32][136],
                                             FragC& acc0, FragC& acc1,
                                             int warpM, int warpN) {
    const int tid  = threadIdx.x;
    const int arow = tid >> 3;           // 0..31
    const int acol = (tid & 7) << 2;     // 0..28
    const int brow = tid >> 5;           // 0..7 (+8r)
    const int bcol = (tid & 31) << 2;    // 0..124

    float4 aReg = *(const float4*)(A + (size_t)(rows0 + arow) * lda + acol);
    float4 bReg[4];
#pragma unroll
    for (int r = 0; r < 4; r++)
        bReg[r] = *(const float4*)(W + (size_t)(brow + 8 * r) * N + cols0 + bcol);

    // fill buffer 0
    *(float4*)&As[0][arow][acol] = tf32r4(aReg);
#pragma unroll
    for (int r = 0; r < 4; r++)
        *(float4*)&Bs[0][brow + 8 * r][bcol] = tf32r4(bReg[r]);
    __syncthreads();

    int buf = 0;
    for (int k0 = 0; k0 < K; k0 += 32) {
        const bool more = (k0 + 32 < K);
        if (more) {
            aReg = *(const float4*)(A + (size_t)(rows0 + arow) * lda + k0 + 32 + acol);
#pragma unroll
            for (int r = 0; r < 4; r++)
                bReg[r] = *(const float4*)(W + (size_t)(k0 + 32 + brow + 8 * r) * N + cols0 + bcol);
        }
#pragma unroll
        for (int ks = 0; ks < 4; ks++) {
            FragA af;
            FragB bf0, bf1;
            wmma::load_matrix_sync(af, &As[buf][warpM * 16][ks * 8], 36);
            wmma::load_matrix_sync(bf0, &Bs[buf][ks * 8][warpN * 32], 136);
            wmma::load_matrix_sync(bf1, &Bs[buf][ks * 8][warpN * 32 + 16], 136);
            wmma::mma_sync(acc0, af, bf0, acc0);
            wmma::mma_sync(acc1, af, bf1, acc1);
        }
        if (more) {
            *(float4*)&As[buf ^ 1][arow][acol] = tf32r4(aReg);
#pragma unroll
            for (int r = 0; r < 4; r++)
                *(float4*)&Bs[buf ^ 1][brow + 8 * r][bcol] = tf32r4(bReg[r]);
        }
        __syncthreads();
        buf ^= 1;
    }
}

// ---------------------------------------------------------------------------
// Fused kernel 1: blocks 0..111 compute hproj tiles (h @ Wcat1 + bcat1);
// blocks 112..367 compute preds for timestep t-1 (skipped at t==0).
// ---------------------------------------------------------------------------
__global__ void __launch_bounds__(256)
hproj_preds(const float* __restrict__ h, const float* __restrict__ Wcat1,
            const float* __restrict__ bcat1, float* __restrict__ hproj,
            const float* __restrict__ Wfc, const float* __restrict__ bfc,
            float* __restrict__ out, const int* __restrict__ len, int t) {
    __shared__ __align__(16) float As[2][32][36];
    __shared__ __align__(16) float Bs[2][32][136];
    __shared__ float hs[DEC_];

    const int blk = blockIdx.x;
    const int tid = threadIdx.x;

    if (blk < HP_BLOCKS) {
        // ---- hproj GEMM tile ----
        const int rows0 = (blk / 14) * 32;
        const int cols0 = (blk % 14) * 128;
        if (t >= len[rows0] - 1) return;
        const int warp = tid >> 5;
        const int warpM = warp >> 2, warpN = warp & 3;
        FragC acc0, acc1;
        wmma::fill_fragment(acc0, 0.0f);
        wmma::fill_fragment(acc1, 0.0f);
        gemm_tc_tile(h, DEC_, Wcat1, N1_, DEC_, rows0, cols0, As, Bs,
                     acc0, acc1, warpM, warpN);
        wmma::store_matrix_sync(&Bs[0][warpM * 16][warpN * 32], acc0, 136, wmma::mem_row_major);
        wmma::store_matrix_sync(&Bs[0][warpM * 16][warpN * 32 + 16], acc1, 136, wmma::mem_row_major);
        __syncthreads();
        const int r = tid >> 3;
        const int cb = (tid & 7) << 4;
#pragma unroll
        for (int u = 0; u < 4; u++) {
            const int col = cb + u * 4;
            float4 v = *(const float4*)&Bs[0][r][col];
            float4 bv = *(const float4*)(bcat1 + cols0 + col);
            v.x += bv.x; v.y += bv.y; v.z += bv.z; v.w += bv.w;
            *(float4*)(hproj + (size_t)(rows0 + r) * N1_ + cols0 + col) = v;
        }
    } else {
        // ---- preds for t-1 ----
        if (t == 0) return;
        const int b = blk - HP_BLOCKS;
        const int tp = t - 1;
        float* o = out + ((size_t)b * T_ + tp) * V_;
        if (tp >= len[b] - 1) {
            if (tid < V_) o[tid] = 0.0f;
            return;
        }
        hs[tid] = h[(size_t)b * DEC_ + tid];
        hs[tid + 256] = h[(size_t)b * DEC_ + tid + 256];
        __syncthreads();
        if (tid < V_) {
            float acc = bfc[tid];
#pragma unroll 8
            for (int k = 0; k < DEC_; k++) acc += hs[k] * Wfc[(size_t)k * V_ + tid];
            o[tid] = acc;
        }
    }
}

// ---------------------------------------------------------------------------
// Fused attention: one block (512 threads) per batch element.
// scores = relu(att1 + att2).Wfull -> softmax over P -> gated awe into
// x[:,0:1536], plus h copy into x[:,1536:2048].
// ---------------------------------------------------------------------------
__global__ void __launch_bounds__(512)
attn_fused(const float* __restrict__ enc, const float* __restrict__ att1,
           const float* __restrict__ Wfull, const float* __restrict__ hproj,
           const float* __restrict__ h, float* __restrict__ x,
           const int* __restrict__ len, int t) {
    const int b = blockIdx.x;
    if (t >= len[b] - 1) return;
    const int tid = threadIdx.x;
    const int warp = tid >> 5, lane = tid & 31;

    __shared__ float att2s[ATT_];
    __shared__ float wf[ATT_];
    __shared__ float es[P_ + 4];

    if (tid < ATT_) {
        att2s[tid] = hproj[(size_t)b * N1_ + tid];
        wf[tid] = Wfull[tid];
    }
    __syncthreads();

    // scores: 16 warps cover P=100 in 7 rounds
    for (int p = warp; p < P_; p += 16) {
        const float* a1 = att1 + ((size_t)(b * P_ + p)) * ATT_;
        float part = 0.0f;
#pragma unroll 4
        for (int j = lane; j < ATT_; j += 32)
            part += fmaxf(a1[j] + att2s[j], 0.0f) * wf[j];
#pragma unroll
        for (int o = 16; o; o >>= 1) part += __shfl_xor_sync(0xffffffffu, part, o);
        if (lane == 0) es[p] = part;
    }
    __syncthreads();

    // softmax over P (warp 0)
    if (tid < 32) {
        float m = -1e30f;
        for (int p = tid; p < P_; p += 32) m = fmaxf(m, es[p]);
#pragma unroll
        for (int o = 16; o; o >>= 1) m = fmaxf(m, __shfl_xor_sync(0xffffffffu, m, o));
        float s = 0.0f;
        for (int p = tid; p < P_; p += 32) {
            float ex = expf(es[p] - m);
            es[p] = ex;
            s += ex;
        }
#pragma unroll
        for (int o = 16; o; o >>= 1) s += __shfl_xor_sync(0xffffffffu, s, o);
        float inv = 1.0f / s;
        for (int p = tid; p < P_; p += 32) es[p] *= inv;
    }
    __syncthreads();

    // h copy into x's recurrent slice (one element per thread)
    x[(size_t)b * K2_ + 1536 + tid] = h[(size_t)b * DEC_ + tid];

    // gated awe: 384 float4 lanes cover ENC=1536
    if (tid < ENC_ / 4) {
        const float4* ep = (const float4*)(enc + ((size_t)b * P_) * ENC_);
        float4 acc = make_float4(0.f, 0.f, 0.f, 0.f);
#pragma unroll 4
        for (int p = 0; p < P_; p++) {
            float4 v = ep[(size_t)p * (ENC_ / 4) + tid];
            float a = es[p];
            acc.x += a * v.x; acc.y += a * v.y; acc.z += a * v.z; acc.w += a * v.w;
        }
        const int col = tid * 4;
        float4 gl = *(const float4*)(hproj + (size_t)b * N1_ + ATT_ + col);
        float4 o;
        o.x = acc.x * sigmoidf_(gl.x);
        o.y = acc.y * sigmoidf_(gl.y);
        o.z = acc.z * sigmoidf_(gl.z);
        o.w = acc.w * sigmoidf_(gl.w);
        *(float4*)(x + (size_t)b * K2_ + col) = o;
    }
}

// ---------------------------------------------------------------------------
// Fused gates GEMM (tf32) + LSTM cell.
// ---------------------------------------------------------------------------
__global__ void __launch_bounds__(256)
gates_tc(const float* __restrict__ x, const float* __restrict__ W,
         const float* __restrict__ embW, const int* __restrict__ caps,
         float* __restrict__ h, float* __restrict__ c,
         const int* __restrict__ len, int t) {
    __shared__ __align__(16) float As[2][32][36];
    __shared__ __align__(16) float Bs[2][32][136];
    const int rows0 = blockIdx.y * 32;
    if (t >= len[rows0] - 1) return;
    const int cols0 = blockIdx.x * 128;
    const int warp = threadIdx.x >> 5;
    const int warpM = warp >> 2, warpN = warp & 3;

    FragC acc0, acc1;
    wmma::fill_fragment(acc0, 0.0f);
    wmma::fill_fragment(acc1, 0.0f);
    gemm_tc_tile(x, K2_, W, N2_, K2_, rows0, cols0, As, Bs, acc0, acc1, warpM, warpN);

    wmma::store_matrix_sync(&Bs[0][warpM * 16][warpN * 32], acc0, 136, wmma::mem_row_major);
    wmma::store_matrix_sync(&Bs[0][warpM * 16][warpN * 32 + 16], acc1, 136, wmma::mem_row_major);
    __syncthreads();

    const int tid = threadIdx.x;
    const int r = tid >> 3;
    const int cb = (tid & 7) << 4;
    const int b = rows0 + r;
    if (t >= len[b] - 1) return;
    const int token = caps[b * T1_ + t];

#pragma unroll
    for (int uu = 0; uu < 4; uu++) {
        const int cp = cols0 + cb + uu * 4;
        const int d = cp >> 2;
        float4 gv = *(const float4*)&Bs[0][r][cb + uu * 4];
        float4 ew = *(const float4*)(embW + (size_t)token * N2_ + cp);
        float vi = gv.x + ew.x;
        float vf = gv.y + ew.y;
        float vg = gv.z + ew.z;
        float vo = gv.w + ew.w;
        float c_old = c[(size_t)b * DEC_ + d];
        float ii = sigmoidf_(vi);
        float ff = sigmoidf_(vf);
        float gg = tanhf(vg);
        float oo = sigmoidf_(vo);
        float cn = ff * c_old + ii * gg;
        float hn = oo * tanhf(cn);
        c[(size_t)b * DEC_ + d] = cn;
        h[(size_t)b * DEC_ + d] = hn;
    }
}

// ---------------------------------------------------------------------------
// preds[b,t,:] = active ? h[b,:] @ W_fc + b_fc : 0   (final-step flush)
// ---------------------------------------------------------------------------
__global__ void preds_kernel(const float* __restrict__ Wfc, const float* __restrict__ bfc,
                             const float* __restrict__ h, float* __restrict__ out,
                             const int* __restrict__ len, int t) {
    const int b = blockIdx.x;
    const int tid = threadIdx.x;
    float* o = out + ((size_t)b * T_ + t) * V_;
    if (t >= len[b] - 1) {
        if (tid < V_) o[tid] = 0.0f;
        return;
    }
    __shared__ float hs[DEC_];
    hs[tid] = h[(size_t)b * DEC_ + tid];
    hs[tid + 256] = h[(size_t)b * DEC_ + tid + 256];
    __syncthreads();
    if (tid < V_) {
        float acc = bfc[tid];
#pragma unroll 8
        for (int k = 0; k < DEC_; k++) acc += hs[k] * Wfc[(size_t)k * V_ + tid];
        o[tid] = acc;
    }
}

// ---------------------------------------------------------------------------
// Merged precompute GEMMs: blocks 0..31 h0, 32..63 c0, 64..1663 att1.
// ---------------------------------------------------------------------------
__global__ void __launch_bounds__(256)
gemm_combo(const float* __restrict__ mean,
           const float* __restrict__ W_init_h, const float* __restrict__ b_init_h,
           float* __restrict__ h,
           const float* __restrict__ W_init_c, const float* __restrict__ b_init_c,
           float* __restrict__ c,
           const float* __restrict__ enc,
           const float* __restrict__ W_enc_att, const float* __restrict__ b_enc_att,
           float* __restrict__ att1) {
    __shared__ __align__(16) float As[2][32][36];
    __shared__ __align__(16) float Bs[2][32][136];
    const int blk = blockIdx.x;
    const float* A;
    const float* W;
    const float* bias;
    float* C;
    int N, rows0, cols0;
    if (blk < 32) {
        A = mean; W = W_init_h; bias = b_init_h; C = h; N = DEC_;
        rows0 = (blk & 7) * 32; cols0 = (blk >> 3) * 128;
    } else if (blk < 64) {
        A = mean; W = W_init_c; bias = b_init_c; C = c; N = DEC_;
        rows0 = ((blk - 32) & 7) * 32; cols0 = ((blk - 32) >> 3) * 128;
    } else {
        const int u = blk - 64;           // 0..1599
        A = enc; W = W_enc_att; bias = b_enc_att; C = att1; N = ATT_;
        rows0 = (u % 800) * 32; cols0 = (u / 800) * 128;
    }
    const int warp = threadIdx.x >> 5;
    const int warpM = warp >> 2, warpN = warp & 3;
    FragC acc0, acc1;
    wmma::fill_fragment(acc0, 0.0f);
    wmma::fill_fragment(acc1, 0.0f);
    gemm_tc_tile(A, ENC_, W, N, ENC_, rows0, cols0, As, Bs, acc0, acc1, warpM, warpN);

    wmma::store_matrix_sync(&Bs[0][warpM * 16][warpN * 32], acc0, 136, wmma::mem_row_major);
    wmma::store_matrix_sync(&Bs[0][warpM * 16][warpN * 32 + 16], acc1, 136, wmma::mem_row_major);
    __syncthreads();

    const int tid = threadIdx.x;
    const int r = tid >> 3;
    const int cb = (tid & 7) << 4;
#pragma unroll
    for (int u = 0; u < 4; u++) {
        const int col = cb + u * 4;
        float4 v = *(const float4*)&Bs[0][r][col];
        float4 bv = *(const float4*)(bias + cols0 + col);
        v.x += bv.x; v.y += bv.y; v.z += bv.z; v.w += bv.w;
        *(float4*)(C + (size_t)(rows0 + r) * N + cols0 + col) = v;
    }
}

// ---------------------------------------------------------------------------
// Merged misc precompute: mean (1536 blocks) | wcat1 (3584) | wcat2 (16384).
// ---------------------------------------------------------------------------
#define PM_MEAN  1536
#define PM_WCAT1 3584
#define PM_GRID  (PM_MEAN + PM_WCAT1 + 16384)
__global__ void prep_misc(const float* __restrict__ enc, float* __restrict__ mean,
                          const float* __restrict__ Wda, const float* __restrict__ Wfb,
                          const float* __restrict__ bda, const float* __restrict__ bfb,
                          float* __restrict__ Wc1, float* __restrict__ bc1,
                          const float* __restrict__ Wih, const float* __restrict__ Whh,
                          float* __restrict__ Wc2) {
    const int blk = blockIdx.x;
    const int tid = threadIdx.x;
    if (blk < PM_MEAN) {
        const int b = blk / 6;
        const int e = (blk % 6) * 256 + tid;
        const float* ep = enc + ((size_t)b * P_) * ENC_ + e;
        float s = 0.0f;
#pragma unroll 4
        for (int p = 0; p < P_; p++) s += ep[(size_t)p * ENC_];
        mean[(size_t)b * ENC_ + e] = s * (1.0f / P_);
    } else if (blk < PM_MEAN + PM_WCAT1) {
        const int idx = (blk - PM_MEAN) * 256 + tid;     // < DEC_*N1_
        const int k = idx / N1_, n = idx % N1_;
        Wc1[idx] = (n < ATT_) ? Wda[k * ATT_ + n] : Wfb[k * ENC_ + (n - ATT_)];
        if (k == 0) bc1[n] = (n < ATT_) ? bda[n] : bfb[n - ATT_];
    } else {
        const int idx = (blk - PM_MEAN - PM_WCAT1) * 256 + tid;   // < K2_*N2_
        const int k = idx / N2_, cp = idx % N2_;
        const int dd = cp >> 2, g = cp & 3;
        const int oc = g * DEC_ + dd;
        Wc2[idx] = (k < 1536) ? Wih[(size_t)(256 + k) * N2_ + oc]
                              : Whh[(size_t)(k - 1536) * N2_ + oc];
    }
}

// embW[v, d*4+g] = sum_k emb[v,k] * W_ih[k, g*512+d] + b_ih + b_hh
__global__ void embw_kernel(const float* __restrict__ emb, const float* __restrict__ Wih,
                            const float* __restrict__ bih, const float* __restrict__ bhh,
                            float* __restrict__ out) {
    const int oc = blockIdx.x * 256 + threadIdx.x;   // 0..2047
    const int v0 = blockIdx.y * 8;
    __shared__ float er[8][EMB_];
#pragma unroll
    for (int r = 0; r < 8; r++) {
        int v = v0 + r;
        er[r][threadIdx.x] = (v < V_) ? emb[(size_t)v * EMB_ + threadIdx.x] : 0.0f;
    }
    __syncthreads();
    float base = bih[oc] + bhh[oc];
    float acc[8];
#pragma unroll
    for (int r = 0; r < 8; r++) acc[r] = base;
    for (int k = 0; k < EMB_; k++) {
        float w = Wih[(size_t)k * N2_ + oc];
#pragma unroll
        for (int r = 0; r < 8; r++) acc[r] += er[r][k] * w;
    }
    const int dd = oc & (DEC_ - 1);
    const int g = oc >> 9;
#pragma unroll
    for (int r = 0; r < 8; r++) {
        int v = v0 + r;
        if (v < V_) out[(size_t)v * N2_ + dd * 4 + g] = acc[r];
    }
}

// ---------------------------------------------------------------------------
extern "C" void kernel_launch(void* const* d_in, const int* in_sizes, int n_in,
                              void* d_out, int out_size) {
    const float* enc        = (const float*)d_in[0];
    const int*   caps       = (const int*)d_in[1];
    const int*   lens       = (const int*)d_in[2];
    const float* emb        = (const float*)d_in[3];
    const float* W_enc_att  = (const float*)d_in[4];
    const float* b_enc_att  = (const float*)d_in[5];
    const float* W_dec_att  = (const float*)d_in[6];
    const float* b_dec_att  = (const float*)d_in[7];
    const float* W_full_att = (const float*)d_in[8];
    // d_in[9] = b_full_att (softmax-invariant; unused)
    const float* W_init_h   = (const float*)d_in[10];
    const float* b_init_h   = (const float*)d_in[11];
    const float* W_init_c   = (const float*)d_in[12];
    const float* b_init_c   = (const float*)d_in[13];
    const float* W_f_beta   = (const float*)d_in[14];
    const float* b_f_beta   = (const float*)d_in[15];
    const float* W_ih       = (const float*)d_in[16];
    const float* b_ih       = (const float*)d_in[17];
    const float* W_hh       = (const float*)d_in[18];
    const float* b_hh       = (const float*)d_in[19];
    const float* W_fc       = (const float*)d_in[20];
    const float* b_fc       = (const float*)d_in[21];
    float* out = (float*)d_out;

    float *ph, *pc, *pmean, *patt1, *phproj, *px, *pWcat1, *pbcat1, *pWcat2, *pembW;
    cudaGetSymbolAddress((void**)&ph,     g_h);
    cudaGetSymbolAddress((void**)&pc,     g_c);
    cudaGetSymbolAddress((void**)&pmean,  g_mean);
    cudaGetSymbolAddress((void**)&patt1,  g_att1);
    cudaGetSymbolAddress((void**)&phproj, g_hproj);
    cudaGetSymbolAddress((void**)&px,     g_x);
    cudaGetSymbolAddress((void**)&pWcat1, g_Wcat1);
    cudaGetSymbolAddress((void**)&pbcat1, g_bcat1);
    cudaGetSymbolAddress((void**)&pWcat2, g_Wcat2);
    cudaGetSymbolAddress((void**)&pembW,  g_embW);

    // ---- precompute: 3 launches ----
    prep_misc<<<PM_GRID, 256>>>(enc, pmean, W_dec_att, W_f_beta, b_dec_att, b_f_beta,
                                pWcat1, pbcat1, W_ih, W_hh, pWcat2);
    embw_kernel<<<dim3(N2_ / 256, (V_ + 7) / 8), 256>>>(emb, W_ih, b_ih, b_hh, pembW);
    gemm_combo<<<64 + 1600, 256>>>(pmean, W_init_h, b_init_h, ph,
                                   W_init_c, b_init_c, pc,
                                   enc, W_enc_att, b_enc_att, patt1);

    // ---- timestep loop: 3 launches/step ----
    for (int t = 0; t < T_; t++) {
        hproj_preds<<<HPP_GRID, 256>>>(ph, pWcat1, pbcat1, phproj, W_fc, b_fc, out, lens, t);
        attn_fused<<<B_, 512>>>(enc, patt1, W_full_att, phproj, ph, px, lens, t);
        gates_tc<<<dim3(N2_ / 128, B_ / 32), 256>>>(px, pWcat2, pembW, caps, ph, pc,
                                                    lens, t);
    }
    // final preds flush
    preds_kernel<<<B_, 256>>>(W_fc, b_fc, ph, out, lens, T_ - 1);
}

// round 13
// speedup vs baseline: 1.1332x; 1.1332x over previous
#include <cuda_runtime.h>
#include <math.h>
#include <mma.h>

using namespace nvcuda;

// Problem constants
#define B_    256
#define P_    100
#define ENC_  1536
#define DEC_  512
#define ATT_  256
#define EMB_  256
#define V_    193
#define VP_   256    // padded vocab for preds GEMM
#define T_    150
#define T1_   151
#define N1_   1792   // att2(256) + f_beta(1536)
#define K2_   2048   // awe(1536) + h(512)
#define N2_   2048   // 4*DEC gate-interleaved

#define HP_BLOCKS 112            // hproj tiles
#define PR_BLOCKS 16             // preds GEMM tiles (8 M x 2 N)
#define HPP_GRID (HP_BLOCKS + PR_BLOCKS)

// Scratch (device globals: allocation-free per harness rules)
__device__ float g_h[B_ * DEC_];
__device__ float g_c[B_ * DEC_];
__device__ float g_mean[B_ * ENC_];
__device__ float g_att1[B_ * P_ * ATT_];
__device__ float g_hproj[B_ * N1_];
__device__ float g_x[B_ * K2_];          // [gated awe (1536) | h (512)]
__device__ float g_Wcat1[DEC_ * N1_];    // [W_dec_att | W_f_beta]
__device__ float g_bcat1[N1_];
__device__ float g_Wcat2[K2_ * N2_];     // rows: [W_ih_enc ; W_hh], cols interleaved d*4+g
__device__ float g_embW[V_ * N2_];       // emb@W_ih_emb + b_ih + b_hh, cols interleaved
__device__ float g_Wfc[DEC_ * VP_];      // W_fc padded to 256 cols
__device__ float g_bfc[VP_];             // b_fc padded

__device__ __forceinline__ float sigmoidf_(float x) { return 1.0f / (1.0f + expf(-x)); }

__device__ __forceinline__ float tf32r(float x) {
    unsigned int u = __float_as_uint(x), v;
    asm("cvt.rna.tf32.f32 %0, %1;" : "=r"(v) : "r"(u));
    return __uint_as_float(v);
}
__device__ __forceinline__ float4 tf32r4(float4 v) {
    return make_float4(tf32r(v.x), tf32r(v.y), tf32r(v.z), tf32r(v.w));
}

typedef wmma::fragment<wmma::matrix_a, 16, 16, 8, wmma::precision::tf32, wmma::row_major> FragA;
typedef wmma::fragment<wmma::matrix_b, 16, 16, 8, wmma::precision::tf32, wmma::row_major> FragB;
typedef wmma::fragment<wmma::accumulator, 16, 16, 8, float> FragC;

// ---------------------------------------------------------------------------
// tf32 tensor-core 32x128 GEMM tile, BK=32, 256 threads = 8 warps (2 M x 4 N).
// Single-buffered (R9-proven).
// ---------------------------------------------------------------------------
__device__ __forceinline__ void gemm_tc_tile(const float* __restrict__ A, int lda,
                                             const float* __restrict__ W, int N, int K,
                                             int rows0, int cols0,
                                             float (*As)[36], float (*Bs)[136],
                                             FragC& acc0, FragC& acc1,
                                             int warpM, int warpN) {
    const int tid  = threadIdx.x;
    const int arow = tid >> 3;           // 0..31
    const int acol = (tid & 7) << 2;     // 0..28
    const int brow = tid >> 5;           // 0..7 (+8r)
    const int bcol = (tid & 31) << 2;    // 0..124

    float4 aReg = *(const float4*)(A + (size_t)(rows0 + arow) * lda + acol);
    float4 bReg[4];
#pragma unroll
    for (int r = 0; r < 4; r++)
        bReg[r] = *(const float4*)(W + (size_t)(brow + 8 * r) * N + cols0 + bcol);

    for (int k0 = 0; k0 < K; k0 += 32) {
        *(float4*)&As[arow][acol] = tf32r4(aReg);
#pragma unroll
        for (int r = 0; r < 4; r++)
            *(float4*)&Bs[brow + 8 * r][bcol] = tf32r4(bReg[r]);
        __syncthreads();
        if (k0 + 32 < K) {
            aReg = *(const float4*)(A + (size_t)(rows0 + arow) * lda + k0 + 32 + acol);
#pragma unroll
            for (int r = 0; r < 4; r++)
                bReg[r] = *(const float4*)(W + (size_t)(k0 + 32 + brow + 8 * r) * N + cols0 + bcol);
        }
#pragma unroll
        for (int ks = 0; ks < 4; ks++) {
            FragA af;
            FragB bf0, bf1;
            wmma::load_matrix_sync(af, &As[warpM * 16][ks * 8], 36);
            wmma::load_matrix_sync(bf0, &Bs[ks * 8][warpN * 32], 136);
            wmma::load_matrix_sync(bf1, &Bs[ks * 8][warpN * 32 + 16], 136);
            wmma::mma_sync(acc0, af, bf0, acc0);
            wmma::mma_sync(acc1, af, bf1, acc1);
        }
        __syncthreads();
    }
}

// ---------------------------------------------------------------------------
// preds GEMM tile (shared by hproj_preds and the final flush):
// out[b, tp, :] = active ? h @ Wfc_pad + bfc_pad : 0, for the 32x128 tile at
// (rows0, cols0). Whole-tile-inactive short-circuits to zero-fill.
// ---------------------------------------------------------------------------
__device__ __forceinline__ void preds_tile(const float* __restrict__ h,
                                           const float* __restrict__ Wfc,
                                           const float* __restrict__ bfc,
                                           float* __restrict__ out,
                                           const int* __restrict__ len, int tp,
                                           int rows0, int cols0,
                                           float (*As)[36], float (*Bs)[136]) {
    const int tid = threadIdx.x;
    const int r = tid >> 3;            // 0..31
    const int cb = (tid & 7) << 4;     // 0..112
    const int b = rows0 + r;
    float* o = out + ((size_t)b * T_ + tp) * V_;

    if (tp >= len[rows0] - 1) {
        // entire row-tile inactive: zero-fill (out is poisoned before timing)
#pragma unroll
        for (int u = 0; u < 16; u++) {
            const int col = cols0 + cb + u;
            if (col < V_) o[col] = 0.0f;
        }
        return;
    }

    const int warp = tid >> 5;
    const int warpM = warp >> 2, warpN = warp & 3;
    FragC acc0, acc1;
    wmma::fill_fragment(acc0, 0.0f);
    wmma::fill_fragment(acc1, 0.0f);
    gemm_tc_tile(h, DEC_, Wfc, VP_, DEC_, rows0, cols0, As, Bs, acc0, acc1, warpM, warpN);
    wmma::store_matrix_sync(&Bs[warpM * 16][warpN * 32], acc0, 136, wmma::mem_row_major);
    wmma::store_matrix_sync(&Bs[warpM * 16][warpN * 32 + 16], acc1, 136, wmma::mem_row_major);
    __syncthreads();

    const bool act = (tp < len[b] - 1);
#pragma unroll
    for (int u = 0; u < 16; u++) {
        const int col = cols0 + cb + u;
        if (col < V_) o[col] = act ? (Bs[r][cb + u] + bfc[col]) : 0.0f;
    }
}

// ---------------------------------------------------------------------------
// Fused kernel 1: blocks 0..111 hproj tiles (h @ Wcat1 + bcat1);
// blocks 112..127 preds GEMM tiles for timestep t-1 (skipped at t==0).
// Both only read h -> dependency-clean in one launch.
// ---------------------------------------------------------------------------
__global__ void __launch_bounds__(256)
hproj_preds(const float* __restrict__ h, const float* __restrict__ Wcat1,
            const float* __restrict__ bcat1, float* __restrict__ hproj,
            const float* __restrict__ Wfc, const float* __restrict__ bfc,
            float* __restrict__ out, const int* __restrict__ len, int t) {
    __shared__ __align__(16) float As[32][36];
    __shared__ __align__(16) float Bs[32][136];

    const int blk = blockIdx.x;
    const int tid = threadIdx.x;

    if (blk < HP_BLOCKS) {
        // ---- hproj GEMM tile ----
        const int rows0 = (blk / 14) * 32;
        const int cols0 = (blk % 14) * 128;
        if (t >= len[rows0] - 1) return;
        const int warp = tid >> 5;
        const int warpM = warp >> 2, warpN = warp & 3;
        FragC acc0, acc1;
        wmma::fill_fragment(acc0, 0.0f);
        wmma::fill_fragment(acc1, 0.0f);
        gemm_tc_tile(h, DEC_, Wcat1, N1_, DEC_, rows0, cols0, As, Bs,
                     acc0, acc1, warpM, warpN);
        wmma::store_matrix_sync(&Bs[warpM * 16][warpN * 32], acc0, 136, wmma::mem_row_major);
        wmma::store_matrix_sync(&Bs[warpM * 16][warpN * 32 + 16], acc1, 136, wmma::mem_row_major);
        __syncthreads();
        const int r = tid >> 3;
        const int cb = (tid & 7) << 4;
#pragma unroll
        for (int u = 0; u < 4; u++) {
            const int col = cb + u * 4;
            float4 v = *(const float4*)&Bs[r][col];
            float4 bv = *(const float4*)(bcat1 + cols0 + col);
            v.x += bv.x; v.y += bv.y; v.z += bv.z; v.w += bv.w;
            *(float4*)(hproj + (size_t)(rows0 + r) * N1_ + cols0 + col) = v;
        }
    } else {
        // ---- preds GEMM tile for t-1 ----
        if (t == 0) return;
        const int pblk = blk - HP_BLOCKS;           // 0..15
        const int rows0 = (pblk & 7) * 32;
        const int cols0 = (pblk >> 3) * 128;
        preds_tile(h, Wfc, bfc, out, len, t - 1, rows0, cols0, As, Bs);
    }
}

// Final preds flush for tp = T-1 (16 blocks).
__global__ void __launch_bounds__(256)
preds_gemm(const float* __restrict__ h, const float* __restrict__ Wfc,
           const float* __restrict__ bfc, float* __restrict__ out,
           const int* __restrict__ len, int tp) {
    __shared__ __align__(16) float As[32][36];
    __shared__ __align__(16) float Bs[32][136];
    const int pblk = blockIdx.x;
    const int rows0 = (pblk & 7) * 32;
    const int cols0 = (pblk >> 3) * 128;
    preds_tile(h, Wfc, bfc, out, len, tp, rows0, cols0, As, Bs);
}

// ---------------------------------------------------------------------------
// Fused attention: one block (512 threads) per batch element.
// scores -> softmax -> gated awe into x[:,0:1536], h copy into x[:,1536:2048].
// ---------------------------------------------------------------------------
__global__ void __launch_bounds__(512)
attn_fused(const float* __restrict__ enc, const float* __restrict__ att1,
           const float* __restrict__ Wfull, const float* __restrict__ hproj,
           const float* __restrict__ h, float* __restrict__ x,
           const int* __restrict__ len, int t) {
    const int b = blockIdx.x;
    if (t >= len[b] - 1) return;
    const int tid = threadIdx.x;
    const int warp = tid >> 5, lane = tid & 31;

    __shared__ float att2s[ATT_];
    __shared__ float wf[ATT_];
    __shared__ float es[P_ + 4];

    if (tid < ATT_) {
        att2s[tid] = hproj[(size_t)b * N1_ + tid];
        wf[tid] = Wfull[tid];
    }
    __syncthreads();

    for (int p = warp; p < P_; p += 16) {
        const float* a1 = att1 + ((size_t)(b * P_ + p)) * ATT_;
        float part = 0.0f;
#pragma unroll 4
        for (int j = lane; j < ATT_; j += 32)
            part += fmaxf(a1[j] + att2s[j], 0.0f) * wf[j];
#pragma unroll
        for (int o = 16; o; o >>= 1) part += __shfl_xor_sync(0xffffffffu, part, o);
        if (lane == 0) es[p] = part;
    }
    __syncthreads();

    if (tid < 32) {
        float m = -1e30f;
        for (int p = tid; p < P_; p += 32) m = fmaxf(m, es[p]);
#pragma unroll
        for (int o = 16; o; o >>= 1) m = fmaxf(m, __shfl_xor_sync(0xffffffffu, m, o));
        float s = 0.0f;
        for (int p = tid; p < P_; p += 32) {
            float ex = expf(es[p] - m);
            es[p] = ex;
            s += ex;
        }
#pragma unroll
        for (int o = 16; o; o >>= 1) s += __shfl_xor_sync(0xffffffffu, s, o);
        float inv = 1.0f / s;
        for (int p = tid; p < P_; p += 32) es[p] *= inv;
    }
    __syncthreads();

    x[(size_t)b * K2_ + 1536 + tid] = h[(size_t)b * DEC_ + tid];

    if (tid < ENC_ / 4) {
        const float4* ep = (const float4*)(enc + ((size_t)b * P_) * ENC_);
        float4 acc = make_float4(0.f, 0.f, 0.f, 0.f);
#pragma unroll 4
        for (int p = 0; p < P_; p++) {
            float4 v = ep[(size_t)p * (ENC_ / 4) + tid];
            float a = es[p];
            acc.x += a * v.x; acc.y += a * v.y; acc.z += a * v.z; acc.w += a * v.w;
        }
        const int col = tid * 4;
        float4 gl = *(const float4*)(hproj + (size_t)b * N1_ + ATT_ + col);
        float4 o;
        o.x = acc.x * sigmoidf_(gl.x);
        o.y = acc.y * sigmoidf_(gl.y);
        o.z = acc.z * sigmoidf_(gl.z);
        o.w = acc.w * sigmoidf_(gl.w);
        *(float4*)(x + (size_t)b * K2_ + col) = o;
    }
}

// ---------------------------------------------------------------------------
// Fused gates GEMM (tf32) + LSTM cell.
// ---------------------------------------------------------------------------
__global__ void __launch_bounds__(256)
gates_tc(const float* __restrict__ x, const float* __restrict__ W,
         const float* __restrict__ embW, const int* __restrict__ caps,
         float* __restrict__ h, float* __restrict__ c,
         const int* __restrict__ len, int t) {
    __shared__ __align__(16) float As[32][36];
    __shared__ __align__(16) float Bs[32][136];
    const int rows0 = blockIdx.y * 32;
    if (t >= len[rows0] - 1) return;
    const int cols0 = blockIdx.x * 128;
    const int warp = threadIdx.x >> 5;
    const int warpM = warp >> 2, warpN = warp & 3;

    FragC acc0, acc1;
    wmma::fill_fragment(acc0, 0.0f);
    wmma::fill_fragment(acc1, 0.0f);
    gemm_tc_tile(x, K2_, W, N2_, K2_, rows0, cols0, As, Bs, acc0, acc1, warpM, warpN);

    wmma::store_matrix_sync(&Bs[warpM * 16][warpN * 32], acc0, 136, wmma::mem_row_major);
    wmma::store_matrix_sync(&Bs[warpM * 16][warpN * 32 + 16], acc1, 136, wmma::mem_row_major);
    __syncthreads();

    const int tid = threadIdx.x;
    const int r = tid >> 3;
    const int cb = (tid & 7) << 4;
    const int b = rows0 + r;
    if (t >= len[b] - 1) return;
    const int token = caps[b * T1_ + t];

#pragma unroll
    for (int uu = 0; uu < 4; uu++) {
        const int cp = cols0 + cb + uu * 4;
        const int d = cp >> 2;
        float4 gv = *(const float4*)&Bs[r][cb + uu * 4];
        float4 ew = *(const float4*)(embW + (size_t)token * N2_ + cp);
        float vi = gv.x + ew.x;
        float vf = gv.y + ew.y;
        float vg = gv.z + ew.z;
        float vo = gv.w + ew.w;
        float c_old = c[(size_t)b * DEC_ + d];
        float ii = sigmoidf_(vi);
        float ff = sigmoidf_(vf);
        float gg = tanhf(vg);
        float oo = sigmoidf_(vo);
        float cn = ff * c_old + ii * gg;
        float hn = oo * tanhf(cn);
        c[(size_t)b * DEC_ + d] = cn;
        h[(size_t)b * DEC_ + d] = hn;
    }
}

// ---------------------------------------------------------------------------
// Merged precompute GEMMs: blocks 0..31 h0, 32..63 c0, 64..1663 att1.
// ---------------------------------------------------------------------------
__global__ void __launch_bounds__(256)
gemm_combo(const float* __restrict__ mean,
           const float* __restrict__ W_init_h, const float* __restrict__ b_init_h,
           float* __restrict__ h,
           const float* __restrict__ W_init_c, const float* __restrict__ b_init_c,
           float* __restrict__ c,
           const float* __restrict__ enc,
           const float* __restrict__ W_enc_att, const float* __restrict__ b_enc_att,
           float* __restrict__ att1) {
    __shared__ __align__(16) float As[32][36];
    __shared__ __align__(16) float Bs[32][136];
    const int blk = blockIdx.x;
    const float* A;
    const float* W;
    const float* bias;
    float* C;
    int N, rows0, cols0;
    if (blk < 32) {
        A = mean; W = W_init_h; bias = b_init_h; C = h; N = DEC_;
        rows0 = (blk & 7) * 32; cols0 = (blk >> 3) * 128;
    } else if (blk < 64) {
        A = mean; W = W_init_c; bias = b_init_c; C = c; N = DEC_;
        rows0 = ((blk - 32) & 7) * 32; cols0 = ((blk - 32) >> 3) * 128;
    } else {
        const int u = blk - 64;           // 0..1599
        A = enc; W = W_enc_att; bias = b_enc_att; C = att1; N = ATT_;
        rows0 = (u % 800) * 32; cols0 = (u / 800) * 128;
    }
    const int warp = threadIdx.x >> 5;
    const int warpM = warp >> 2, warpN = warp & 3;
    FragC acc0, acc1;
    wmma::fill_fragment(acc0, 0.0f);
    wmma::fill_fragment(acc1, 0.0f);
    gemm_tc_tile(A, ENC_, W, N, ENC_, rows0, cols0, As, Bs, acc0, acc1, warpM, warpN);

    wmma::store_matrix_sync(&Bs[warpM * 16][warpN * 32], acc0, 136, wmma::mem_row_major);
    wmma::store_matrix_sync(&Bs[warpM * 16][warpN * 32 + 16], acc1, 136, wmma::mem_row_major);
    __syncthreads();

    const int tid = threadIdx.x;
    const int r = tid >> 3;
    const int cb = (tid & 7) << 4;
#pragma unroll
    for (int u = 0; u < 4; u++) {
        const int col = cb + u * 4;
        float4 v = *(const float4*)&Bs[r][col];
        float4 bv = *(const float4*)(bias + cols0 + col);
        v.x += bv.x; v.y += bv.y; v.z += bv.z; v.w += bv.w;
        *(float4*)(C + (size_t)(rows0 + r) * N + cols0 + col) = v;
    }
}

// ---------------------------------------------------------------------------
// Merged misc precompute: mean | wcat1 | wcat2 | Wfc pad.
// ---------------------------------------------------------------------------
#define PM_MEAN  1536
#define PM_WCAT1 3584
#define PM_WCAT2 16384
#define PM_WFC   512
#define PM_GRID  (PM_MEAN + PM_WCAT1 + PM_WCAT2 + PM_WFC)
__global__ void prep_misc(const float* __restrict__ enc, float* __restrict__ mean,
                          const float* __restrict__ Wda, const float* __restrict__ Wfb,
                          const float* __restrict__ bda, const float* __restrict__ bfb,
                          float* __restrict__ Wc1, float* __restrict__ bc1,
                          const float* __restrict__ Wih, const float* __restrict__ Whh,
                          float* __restrict__ Wc2,
                          const float* __restrict__ Wfc, const float* __restrict__ bfc,
                          float* __restrict__ Wfcp, float* __restrict__ bfcp) {
    const int blk = blockIdx.x;
    const int tid = threadIdx.x;
    if (blk < PM_MEAN) {
        const int b = blk / 6;
        const int e = (blk % 6) * 256 + tid;
        const float* ep = enc + ((size_t)b * P_) * ENC_ + e;
        float s = 0.0f;
#pragma unroll 4
        for (int p = 0; p < P_; p++) s += ep[(size_t)p * ENC_];
        mean[(size_t)b * ENC_ + e] = s * (1.0f / P_);
    } else if (blk < PM_MEAN + PM_WCAT1) {
        const int idx = (blk - PM_MEAN) * 256 + tid;     // < DEC_*N1_
        const int k = idx / N1_, n = idx % N1_;
        Wc1[idx] = (n < ATT_) ? Wda[k * ATT_ + n] : Wfb[k * ENC_ + (n - ATT_)];
        if (k == 0) bc1[n] = (n < ATT_) ? bda[n] : bfb[n - ATT_];
    } else if (blk < PM_MEAN + PM_WCAT1 + PM_WCAT2) {
        const int idx = (blk - PM_MEAN - PM_WCAT1) * 256 + tid;   // < K2_*N2_
        const int k = idx / N2_, cp = idx % N2_;
        const int dd = cp >> 2, g = cp & 3;
        const int oc = g * DEC_ + dd;
        Wc2[idx] = (k < 1536) ? Wih[(size_t)(256 + k) * N2_ + oc]
                              : Whh[(size_t)(k - 1536) * N2_ + oc];
    } else {
        const int idx = (blk - PM_MEAN - PM_WCAT1 - PM_WCAT2) * 256 + tid;  // < DEC_*VP_
        const int k = idx / VP_, n = idx % VP_;
        Wfcp[idx] = (n < V_) ? Wfc[k * V_ + n] : 0.0f;
        if (k == 0) bfcp[n] = (n < V_) ? bfc[n] : 0.0f;
    }
}

// embW[v, d*4+g] = sum_k emb[v,k] * W_ih[k, g*512+d] + b_ih + b_hh
__global__ void embw_kernel(const float* __restrict__ emb, const float* __restrict__ Wih,
                            const float* __restrict__ bih, const float* __restrict__ bhh,
                            float* __restrict__ out) {
    const int oc = blockIdx.x * 256 + threadIdx.x;   // 0..2047
    const int v0 = blockIdx.y * 8;
    __shared__ float er[8][EMB_];
#pragma unroll
    for (int r = 0; r < 8; r++) {
        int v = v0 + r;
        er[r][threadIdx.x] = (v < V_) ? emb[(size_t)v * EMB_ + threadIdx.x] : 0.0f;
    }
    __syncthreads();
    float base = bih[oc] + bhh[oc];
    float acc[8];
#pragma unroll
    for (int r = 0; r < 8; r++) acc[r] = base;
    for (int k = 0; k < EMB_; k++) {
        float w = Wih[(size_t)k * N2_ + oc];
#pragma unroll
        for (int r = 0; r < 8; r++) acc[r] += er[r][k] * w;
    }
    const int dd = oc & (DEC_ - 1);
    const int g = oc >> 9;
#pragma unroll
    for (int r = 0; r < 8; r++) {
        int v = v0 + r;
        if (v < V_) out[(size_t)v * N2_ + dd * 4 + g] = acc[r];
    }
}

// ---------------------------------------------------------------------------
extern "C" void kernel_launch(void* const* d_in, const int* in_sizes, int n_in,
                              void* d_out, int out_size) {
    const float* enc        = (const float*)d_in[0];
    const int*   caps       = (const int*)d_in[1];
    const int*   lens       = (const int*)d_in[2];
    const float* emb        = (const float*)d_in[3];
    const float* W_enc_att  = (const float*)d_in[4];
    const float* b_enc_att  = (const float*)d_in[5];
    const float* W_dec_att  = (const float*)d_in[6];
    const float* b_dec_att  = (const float*)d_in[7];
    const float* W_full_att = (const float*)d_in[8];
    // d_in[9] = b_full_att (softmax-invariant; unused)
    const float* W_init_h   = (const float*)d_in[10];
    const float* b_init_h   = (const float*)d_in[11];
    const float* W_init_c   = (const float*)d_in[12];
    const float* b_init_c   = (const float*)d_in[13];
    const float* W_f_beta   = (const float*)d_in[14];
    const float* b_f_beta   = (const float*)d_in[15];
    const float* W_ih       = (const float*)d_in[16];
    const float* b_ih       = (const float*)d_in[17];
    const float* W_hh       = (const float*)d_in[18];
    const float* b_hh       = (const float*)d_in[19];
    const float* W_fc       = (const float*)d_in[20];
    const float* b_fc       = (const float*)d_in[21];
    float* out = (float*)d_out;

    float *ph, *pc, *pmean, *patt1, *phproj, *px, *pWcat1, *pbcat1, *pWcat2, *pembW,
          *pWfc, *pbfc;
    cudaGetSymbolAddress((void**)&ph,     g_h);
    cudaGetSymbolAddress((void**)&pc,     g_c);
    cudaGetSymbolAddress((void**)&pmean,  g_mean);
    cudaGetSymbolAddress((void**)&patt1,  g_att1);
    cudaGetSymbolAddress((void**)&phproj, g_hproj);
    cudaGetSymbolAddress((void**)&px,     g_x);
    cudaGetSymbolAddress((void**)&pWcat1, g_Wcat1);
    cudaGetSymbolAddress((void**)&pbcat1, g_bcat1);
    cudaGetSymbolAddress((void**)&pWcat2, g_Wcat2);
    cudaGetSymbolAddress((void**)&pembW,  g_embW);
    cudaGetSymbolAddress((void**)&pWfc,   g_Wfc);
    cudaGetSymbolAddress((void**)&pbfc,   g_bfc);

    // ---- precompute: 3 launches ----
    prep_misc<<<PM_GRID, 256>>>(enc, pmean, W_dec_att, W_f_beta, b_dec_att, b_f_beta,
                                pWcat1, pbcat1, W_ih, W_hh, pWcat2,
                                W_fc, b_fc, pWfc, pbfc);
    embw_kernel<<<dim3(N2_ / 256, (V_ + 7) / 8), 256>>>(emb, W_ih, b_ih, b_hh, pembW);
    gemm_combo<<<64 + 1600, 256>>>(pmean, W_init_h, b_init_h, ph,
                                   W_init_c, b_init_c, pc,
                                   enc, W_enc_att, b_enc_att, patt1);

    // ---- timestep loop: 3 launches/step ----
    for (int t = 0; t < T_; t++) {
        hproj_preds<<<HPP_GRID, 256>>>(ph, pWcat1, pbcat1, phproj, pWfc, pbfc, out, lens, t);
        attn_fused<<<B_, 512>>>(enc, patt1, W_full_att, phproj, ph, px, lens, t);
        gates_tc<<<dim3(N2_ / 128, B_ / 32), 256>>>(px, pWcat2, pembW, caps, ph, pc,
                                                    lens, t);
    }
    // final preds flush (t = T-1)
    preds_gemm<<<PR_BLOCKS, 256>>>(ph, pWfc, pbfc, out, lens, T_ - 1);
}

// round 14
// speedup vs baseline: 1.5034x; 1.3267x over previous
#include <cuda_runtime.h>
#include <math.h>
#include <mma.h>

using namespace nvcuda;

// Problem constants
#define B_    256
#define P_    100
#define ENC_  1536
#define DEC_  512
#define ATT_  256
#define EMB_  256
#define V_    193
#define VP_   256    // padded vocab for preds GEMM
#define T_    150
#define T1_   151
#define N1_   1792   // att2(256) + f_beta(1536)
#define K2_   2048   // awe(1536) + h(512)
#define N2_   2048   // 4*DEC gate-interleaved
#define KCH_  4      // gates split-K chunks
#define KCS_  512    // K per chunk

#define HP_BLOCKS 112            // hproj tiles
#define PR_BLOCKS 16             // preds GEMM tiles (8 M x 2 N)
#define HPP_GRID (HP_BLOCKS + PR_BLOCKS)

// Scratch (device globals: allocation-free per harness rules)
__device__ float g_h[B_ * DEC_];
__device__ float g_c[B_ * DEC_];
__device__ float g_mean[B_ * ENC_];
__device__ float g_att1[B_ * P_ * ATT_];
__device__ float g_hproj[B_ * N1_];
__device__ float g_x[B_ * K2_];          // [gated awe (1536) | h (512)]
__device__ float g_Wcat1[DEC_ * N1_];    // [W_dec_att | W_f_beta]
__device__ float g_bcat1[N1_];
__device__ float g_Wcat2[K2_ * N2_];     // rows: [W_ih_enc ; W_hh], cols interleaved d*4+g
__device__ float g_embW[V_ * N2_];       // emb@W_ih_emb + b_ih + b_hh, cols interleaved
__device__ float g_Wfc[DEC_ * VP_];      // W_fc padded to 256 cols
__device__ float g_bfc[VP_];             // b_fc padded
__device__ float g_gpart[KCH_ * B_ * N2_];  // gates split-K partials (8 MB)

__device__ __forceinline__ float sigmoidf_(float x) { return 1.0f / (1.0f + expf(-x)); }

__device__ __forceinline__ float tf32r(float x) {
    unsigned int u = __float_as_uint(x), v;
    asm("cvt.rna.tf32.f32 %0, %1;" : "=r"(v) : "r"(u));
    return __uint_as_float(v);
}
__device__ __forceinline__ float4 tf32r4(float4 v) {
    return make_float4(tf32r(v.x), tf32r(v.y), tf32r(v.z), tf32r(v.w));
}

typedef wmma::fragment<wmma::matrix_a, 16, 16, 8, wmma::precision::tf32, wmma::row_major> FragA;
typedef wmma::fragment<wmma::matrix_b, 16, 16, 8, wmma::precision::tf32, wmma::row_major> FragB;
typedef wmma::fragment<wmma::accumulator, 16, 16, 8, float> FragC;

// ---------------------------------------------------------------------------
// tf32 tensor-core 32x128 GEMM tile, BK=32, 256 threads = 8 warps (2 M x 4 N).
// Single-buffered (proven).
// ---------------------------------------------------------------------------
__device__ __forceinline__ void gemm_tc_tile(const float* __restrict__ A, int lda,
                                             const float* __restrict__ W, int N, int K,
                                             int rows0, int cols0,
                                             float (*As)[36], float (*Bs)[136],
                                             FragC& acc0, FragC& acc1,
                                             int warpM, int warpN) {
    const int tid  = threadIdx.x;
    const int arow = tid >> 3;           // 0..31
    const int acol = (tid & 7) << 2;     // 0..28
    const int brow = tid >> 5;           // 0..7 (+8r)
    const int bcol = (tid & 31) << 2;    // 0..124

    float4 aReg = *(const float4*)(A + (size_t)(rows0 + arow) * lda + acol);
    float4 bReg[4];
#pragma unroll
    for (int r = 0; r < 4; r++)
        bReg[r] = *(const float4*)(W + (size_t)(brow + 8 * r) * N + cols0 + bcol);

    for (int k0 = 0; k0 < K; k0 += 32) {
        *(float4*)&As[arow][acol] = tf32r4(aReg);
#pragma unroll
        for (int r = 0; r < 4; r++)
            *(float4*)&Bs[brow + 8 * r][bcol] = tf32r4(bReg[r]);
        __syncthreads();
        if (k0 + 32 < K) {
            aReg = *(const float4*)(A + (size_t)(rows0 + arow) * lda + k0 + 32 + acol);
#pragma unroll
            for (int r = 0; r < 4; r++)
                bReg[r] = *(const float4*)(W + (size_t)(k0 + 32 + brow + 8 * r) * N + cols0 + bcol);
        }
#pragma unroll
        for (int ks = 0; ks < 4; ks++) {
            FragA af;
            FragB bf0, bf1;
            wmma::load_matrix_sync(af, &As[warpM * 16][ks * 8], 36);
            wmma::load_matrix_sync(bf0, &Bs[ks * 8][warpN * 32], 136);
            wmma::load_matrix_sync(bf1, &Bs[ks * 8][warpN * 32 + 16], 136);
            wmma::mma_sync(acc0, af, bf0, acc0);
            wmma::mma_sync(acc1, af, bf1, acc1);
        }
        __syncthreads();
    }
}

// ---------------------------------------------------------------------------
// preds GEMM tile: out[b, tp, :] = active ? h @ Wfc_pad + bfc_pad : 0.
// ---------------------------------------------------------------------------
__device__ __forceinline__ void preds_tile(const float* __restrict__ h,
                                           const float* __restrict__ Wfc,
                                           const float* __restrict__ bfc,
                                           float* __restrict__ out,
                                           const int* __restrict__ len, int tp,
                                           int rows0, int cols0,
                                           float (*As)[36], float (*Bs)[136]) {
    const int tid = threadIdx.x;
    const int r = tid >> 3;            // 0..31
    const int cb = (tid & 7) << 4;     // 0..112
    const int b = rows0 + r;
    float* o = out + ((size_t)b * T_ + tp) * V_;

    if (tp >= len[rows0] - 1) {
#pragma unroll
        for (int u = 0; u < 16; u++) {
            const int col = cols0 + cb + u;
            if (col < V_) o[col] = 0.0f;
        }
        return;
    }

    const int warp = tid >> 5;
    const int warpM = warp >> 2, warpN = warp & 3;
    FragC acc0, acc1;
    wmma::fill_fragment(acc0, 0.0f);
    wmma::fill_fragment(acc1, 0.0f);
    gemm_tc_tile(h, DEC_, Wfc, VP_, DEC_, rows0, cols0, As, Bs, acc0, acc1, warpM, warpN);
    wmma::store_matrix_sync(&Bs[warpM * 16][warpN * 32], acc0, 136, wmma::mem_row_major);
    wmma::store_matrix_sync(&Bs[warpM * 16][warpN * 32 + 16], acc1, 136, wmma::mem_row_major);
    __syncthreads();

    const bool act = (tp < len[b] - 1);
#pragma unroll
    for (int u = 0; u < 16; u++) {
        const int col = cols0 + cb + u;
        if (col < V_) o[col] = act ? (Bs[r][cb + u] + bfc[col]) : 0.0f;
    }
}

// ---------------------------------------------------------------------------
// Fused kernel 1: blocks 0..111 hproj tiles; blocks 112..127 preds tiles (t-1).
// ---------------------------------------------------------------------------
__global__ void __launch_bounds__(256)
hproj_preds(const float* __restrict__ h, const float* __restrict__ Wcat1,
            const float* __restrict__ bcat1, float* __restrict__ hproj,
            const float* __restrict__ Wfc, const float* __restrict__ bfc,
            float* __restrict__ out, const int* __restrict__ len, int t) {
    __shared__ __align__(16) float As[32][36];
    __shared__ __align__(16) float Bs[32][136];

    const int blk = blockIdx.x;
    const int tid = threadIdx.x;

    if (blk < HP_BLOCKS) {
        const int rows0 = (blk / 14) * 32;
        const int cols0 = (blk % 14) * 128;
        if (t >= len[rows0] - 1) return;
        const int warp = tid >> 5;
        const int warpM = warp >> 2, warpN = warp & 3;
        FragC acc0, acc1;
        wmma::fill_fragment(acc0, 0.0f);
        wmma::fill_fragment(acc1, 0.0f);
        gemm_tc_tile(h, DEC_, Wcat1, N1_, DEC_, rows0, cols0, As, Bs,
                     acc0, acc1, warpM, warpN);
        wmma::store_matrix_sync(&Bs[warpM * 16][warpN * 32], acc0, 136, wmma::mem_row_major);
        wmma::store_matrix_sync(&Bs[warpM * 16][warpN * 32 + 16], acc1, 136, wmma::mem_row_major);
        __syncthreads();
        const int r = tid >> 3;
        const int cb = (tid & 7) << 4;
#pragma unroll
        for (int u = 0; u < 4; u++) {
            const int col = cb + u * 4;
            float4 v = *(const float4*)&Bs[r][col];
            float4 bv = *(const float4*)(bcat1 + cols0 + col);
            v.x += bv.x; v.y += bv.y; v.z += bv.z; v.w += bv.w;
            *(float4*)(hproj + (size_t)(rows0 + r) * N1_ + cols0 + col) = v;
        }
    } else {
        if (t == 0) return;
        const int pblk = blk - HP_BLOCKS;           // 0..15
        const int rows0 = (pblk & 7) * 32;
        const int cols0 = (pblk >> 3) * 128;
        preds_tile(h, Wfc, bfc, out, len, t - 1, rows0, cols0, As, Bs);
    }
}

// Final preds flush for tp = T-1 (16 blocks).
__global__ void __launch_bounds__(256)
preds_gemm(const float* __restrict__ h, const float* __restrict__ Wfc,
           const float* __restrict__ bfc, float* __restrict__ out,
           const int* __restrict__ len, int tp) {
    __shared__ __align__(16) float As[32][36];
    __shared__ __align__(16) float Bs[32][136];
    const int pblk = blockIdx.x;
    const int rows0 = (pblk & 7) * 32;
    const int cols0 = (pblk >> 3) * 128;
    preds_tile(h, Wfc, bfc, out, len, tp, rows0, cols0, As, Bs);
}

// ---------------------------------------------------------------------------
// Fused attention: one block (512 threads) per batch element.
// ---------------------------------------------------------------------------
__global__ void __launch_bounds__(512)
attn_fused(const float* __restrict__ enc, const float* __restrict__ att1,
           const float* __restrict__ Wfull, const float* __restrict__ hproj,
           const float* __restrict__ h, float* __restrict__ x,
           const int* __restrict__ len, int t) {
    const int b = blockIdx.x;
    if (t >= len[b] - 1) return;
    const int tid = threadIdx.x;
    const int warp = tid >> 5, lane = tid & 31;

    __shared__ float att2s[ATT_];
    __shared__ float wf[ATT_];
    __shared__ float es[P_ + 4];

    if (tid < ATT_) {
        att2s[tid] = hproj[(size_t)b * N1_ + tid];
        wf[tid] = Wfull[tid];
    }
    __syncthreads();

    for (int p = warp; p < P_; p += 16) {
        const float* a1 = att1 + ((size_t)(b * P_ + p)) * ATT_;
        float part = 0.0f;
#pragma unroll 4
        for (int j = lane; j < ATT_; j += 32)
            part += fmaxf(a1[j] + att2s[j], 0.0f) * wf[j];
#pragma unroll
        for (int o = 16; o; o >>= 1) part += __shfl_xor_sync(0xffffffffu, part, o);
        if (lane == 0) es[p] = part;
    }
    __syncthreads();

    if (tid < 32) {
        float m = -1e30f;
        for (int p = tid; p < P_; p += 32) m = fmaxf(m, es[p]);
#pragma unroll
        for (int o = 16; o; o >>= 1) m = fmaxf(m, __shfl_xor_sync(0xffffffffu, m, o));
        float s = 0.0f;
        for (int p = tid; p < P_; p += 32) {
            float ex = expf(es[p] - m);
            es[p] = ex;
            s += ex;
        }
#pragma unroll
        for (int o = 16; o; o >>= 1) s += __shfl_xor_sync(0xffffffffu, s, o);
        float inv = 1.0f / s;
        for (int p = tid; p < P_; p += 32) es[p] *= inv;
    }
    __syncthreads();

    x[(size_t)b * K2_ + 1536 + tid] = h[(size_t)b * DEC_ + tid];

    if (tid < ENC_ / 4) {
        const float4* ep = (const float4*)(enc + ((size_t)b * P_) * ENC_);
        float4 acc = make_float4(0.f, 0.f, 0.f, 0.f);
#pragma unroll 4
        for (int p = 0; p < P_; p++) {
            float4 v = ep[(size_t)p * (ENC_ / 4) + tid];
            float a = es[p];
            acc.x += a * v.x; acc.y += a * v.y; acc.z += a * v.z; acc.w += a * v.w;
        }
        const int col = tid * 4;
        float4 gl = *(const float4*)(hproj + (size_t)b * N1_ + ATT_ + col);
        float4 o;
        o.x = acc.x * sigmoidf_(gl.x);
        o.y = acc.y * sigmoidf_(gl.y);
        o.z = acc.z * sigmoidf_(gl.z);
        o.w = acc.w * sigmoidf_(gl.w);
        *(float4*)(x + (size_t)b * K2_ + col) = o;
    }
}

// ---------------------------------------------------------------------------
// gates split-K partial GEMM: grid (16 cols, 8 rows, 4 K-chunks).
// Writes raw partials (no bias) to gpart[chunk][b][cp].
// ---------------------------------------------------------------------------
__global__ void __launch_bounds__(256)
gates_partial(const float* __restrict__ x, const float* __restrict__ W,
              float* __restrict__ gpart, const int* __restrict__ len, int t) {
    __shared__ __align__(16) float As[32][36];
    __shared__ __align__(16) float Bs[32][136];
    const int rows0 = blockIdx.y * 32;
    if (t >= len[rows0] - 1) return;
    const int cols0 = blockIdx.x * 128;
    const int kc = blockIdx.z;
    const int warp = threadIdx.x >> 5;
    const int warpM = warp >> 2, warpN = warp & 3;

    FragC acc0, acc1;
    wmma::fill_fragment(acc0, 0.0f);
    wmma::fill_fragment(acc1, 0.0f);
    gemm_tc_tile(x + kc * KCS_, K2_, W + (size_t)(kc * KCS_) * N2_, N2_, KCS_,
                 rows0, cols0, As, Bs, acc0, acc1, warpM, warpN);

    wmma::store_matrix_sync(&Bs[warpM * 16][warpN * 32], acc0, 136, wmma::mem_row_major);
    wmma::store_matrix_sync(&Bs[warpM * 16][warpN * 32 + 16], acc1, 136, wmma::mem_row_major);
    __syncthreads();

    const int tid = threadIdx.x;
    const int r = tid >> 3;
    const int cb = (tid & 7) << 4;
    float* gp = gpart + ((size_t)kc * B_ + (rows0 + r)) * N2_ + cols0;
#pragma unroll
    for (int u = 0; u < 4; u++) {
        *(float4*)(gp + cb + u * 4) = *(const float4*)&Bs[r][cb + u * 4];
    }
}

// ---------------------------------------------------------------------------
// LSTM cell epilogue: sum 4 chunk partials + embW[token], apply cell update.
// One thread per (b, d). Deterministic chunk-sum order.
// ---------------------------------------------------------------------------
__global__ void __launch_bounds__(256)
lstm_cell(const float* __restrict__ gpart, const float* __restrict__ embW,
          const int* __restrict__ caps, float* __restrict__ h, float* __restrict__ c,
          const int* __restrict__ len, int t) {
    const int idx = blockIdx.x * 256 + threadIdx.x;   // 0 .. B_*DEC_-1
    const int b = idx >> 9;
    const int d = idx & (DEC_ - 1);
    if (t >= len[b] - 1) return;
    const int token = caps[b * T1_ + t];

    const float4* gp = (const float4*)gpart;
    const size_t base = (size_t)b * (N2_ / 4) + d;
    float4 s0 = gp[base];
    float4 s1 = gp[(size_t)1 * B_ * (N2_ / 4) + base];
    float4 s2 = gp[(size_t)2 * B_ * (N2_ / 4) + base];
    float4 s3 = gp[(size_t)3 * B_ * (N2_ / 4) + base];
    float4 ew = *(const float4*)(embW + (size_t)token * N2_ + d * 4);

    float vi = ((s0.x + s1.x) + (s2.x + s3.x)) + ew.x;
    float vf = ((s0.y + s1.y) + (s2.y + s3.y)) + ew.y;
    float vg = ((s0.z + s1.z) + (s2.z + s3.z)) + ew.z;
    float vo = ((s0.w + s1.w) + (s2.w + s3.w)) + ew.w;

    float c_old = c[(size_t)b * DEC_ + d];
    float ii = sigmoidf_(vi);
    float ff = sigmoidf_(vf);
    float gg = tanhf(vg);
    float oo = sigmoidf_(vo);
    float cn = ff * c_old + ii * gg;
    float hn = oo * tanhf(cn);
    c[(size_t)b * DEC_ + d] = cn;
    h[(size_t)b * DEC_ + d] = hn;
}

// ---------------------------------------------------------------------------
// Merged precompute GEMMs: blocks 0..31 h0, 32..63 c0, 64..1663 att1.
// ---------------------------------------------------------------------------
__global__ void __launch_bounds__(256)
gemm_combo(const float* __restrict__ mean,
           const float* __restrict__ W_init_h, const float* __restrict__ b_init_h,
           float* __restrict__ h,
           const float* __restrict__ W_init_c, const float* __restrict__ b_init_c,
           float* __restrict__ c,
           const float* __restrict__ enc,
           const float* __restrict__ W_enc_att, const float* __restrict__ b_enc_att,
           float* __restrict__ att1) {
    __shared__ __align__(16) float As[32][36];
    __shared__ __align__(16) float Bs[32][136];
    const int blk = blockIdx.x;
    const float* A;
    const float* W;
    const float* bias;
    float* C;
    int N, rows0, cols0;
    if (blk < 32) {
        A = mean; W = W_init_h; bias = b_init_h; C = h; N = DEC_;
        rows0 = (blk & 7) * 32; cols0 = (blk >> 3) * 128;
    } else if (blk < 64) {
        A = mean; W = W_init_c; bias = b_init_c; C = c; N = DEC_;
        rows0 = ((blk - 32) & 7) * 32; cols0 = ((blk - 32) >> 3) * 128;
    } else {
        const int u = blk - 64;           // 0..1599
        A = enc; W = W_enc_att; bias = b_enc_att; C = att1; N = ATT_;
        rows0 = (u % 800) * 32; cols0 = (u / 800) * 128;
    }
    const int warp = threadIdx.x >> 5;
    const int warpM = warp >> 2, warpN = warp & 3;
    FragC acc0, acc1;
    wmma::fill_fragment(acc0, 0.0f);
    wmma::fill_fragment(acc1, 0.0f);
    gemm_tc_tile(A, ENC_, W, N, ENC_, rows0, cols0, As, Bs, acc0, acc1, warpM, warpN);

    wmma::store_matrix_sync(&Bs[warpM * 16][warpN * 32], acc0, 136, wmma::mem_row_major);
    wmma::store_matrix_sync(&Bs[warpM * 16][warpN * 32 + 16], acc1, 136, wmma::mem_row_major);
    __syncthreads();

    const int tid = threadIdx.x;
    const int r = tid >> 3;
    const int cb = (tid & 7) << 4;
#pragma unroll
    for (int u = 0; u < 4; u++) {
        const int col = cb + u * 4;
        float4 v = *(const float4*)&Bs[r][col];
        float4 bv = *(const float4*)(bias + cols0 + col);
        v.x += bv.x; v.y += bv.y; v.z += bv.z; v.w += bv.w;
        *(float4*)(C + (size_t)(rows0 + r) * N + cols0 + col) = v;
    }
}

// ---------------------------------------------------------------------------
// Merged misc precompute: mean | wcat1 | wcat2 | Wfc pad.
// ---------------------------------------------------------------------------
#define PM_MEAN  1536
#define PM_WCAT1 3584
#define PM_WCAT2 16384
#define PM_WFC   512
#define PM_GRID  (PM_MEAN + PM_WCAT1 + PM_WCAT2 + PM_WFC)
__global__ void prep_misc(const float* __restrict__ enc, float* __restrict__ mean,
                          const float* __restrict__ Wda, const float* __restrict__ Wfb,
                          const float* __restrict__ bda, const float* __restrict__ bfb,
                          float* __restrict__ Wc1, float* __restrict__ bc1,
                          const float* __restrict__ Wih, const float* __restrict__ Whh,
                          float* __restrict__ Wc2,
                          const float* __restrict__ Wfc, const float* __restrict__ bfc,
                          float* __restrict__ Wfcp, float* __restrict__ bfcp) {
    const int blk = blockIdx.x;
    const int tid = threadIdx.x;
    if (blk < PM_MEAN) {
        const int b = blk / 6;
        const int e = (blk % 6) * 256 + tid;
        const float* ep = enc + ((size_t)b * P_) * ENC_ + e;
        float s = 0.0f;
#pragma unroll 4
        for (int p = 0; p < P_; p++) s += ep[(size_t)p * ENC_];
        mean[(size_t)b * ENC_ + e] = s * (1.0f / P_);
    } else if (blk < PM_MEAN + PM_WCAT1) {
        const int idx = (blk - PM_MEAN) * 256 + tid;     // < DEC_*N1_
        const int k = idx / N1_, n = idx % N1_;
        Wc1[idx] = (n < ATT_) ? Wda[k * ATT_ + n] : Wfb[k * ENC_ + (n - ATT_)];
        if (k == 0) bc1[n] = (n < ATT_) ? bda[n] : bfb[n - ATT_];
    } else if (blk < PM_MEAN + PM_WCAT1 + PM_WCAT2) {
        const int idx = (blk - PM_MEAN - PM_WCAT1) * 256 + tid;   // < K2_*N2_
        const int k = idx / N2_, cp = idx % N2_;
        const int dd = cp >> 2, g = cp & 3;
        const int oc = g * DEC_ + dd;
        Wc2[idx] = (k < 1536) ? Wih[(size_t)(256 + k) * N2_ + oc]
                              : Whh[(size_t)(k - 1536) * N2_ + oc];
    } else {
        const int idx = (blk - PM_MEAN - PM_WCAT1 - PM_WCAT2) * 256 + tid;  // < DEC_*VP_
        const int k = idx / VP_, n = idx % VP_;
        Wfcp[idx] = (n < V_) ? Wfc[k * V_ + n] : 0.0f;
        if (k == 0) bfcp[n] = (n < V_) ? bfc[n] : 0.0f;
    }
}

// embW[v, d*4+g] = sum_k emb[v,k] * W_ih[k, g*512+d] + b_ih + b_hh
__global__ void embw_kernel(const float* __restrict__ emb, const float* __restrict__ Wih,
                            const float* __restrict__ bih, const float* __restrict__ bhh,
                            float* __restrict__ out) {
    const int oc = blockIdx.x * 256 + threadIdx.x;   // 0..2047
    const int v0 = blockIdx.y * 8;
    __shared__ float er[8][EMB_];
#pragma unroll
    for (int r = 0; r < 8; r++) {
        int v = v0 + r;
        er[r][threadIdx.x] = (v < V_) ? emb[(size_t)v * EMB_ + threadIdx.x] : 0.0f;
    }
    __syncthreads();
    float base = bih[oc] + bhh[oc];
    float acc[8];
#pragma unroll
    for (int r = 0; r < 8; r++) acc[r] = base;
    for (int k = 0; k < EMB_; k++) {
        float w = Wih[(size_t)k * N2_ + oc];
#pragma unroll
        for (int r = 0; r < 8; r++) acc[r] += er[r][k] * w;
    }
    const int dd = oc & (DEC_ - 1);
    const int g = oc >> 9;
#pragma unroll
    for (int r = 0; r < 8; r++) {
        int v = v0 + r;
        if (v < V_) out[(size_t)v * N2_ + dd * 4 + g] = acc[r];
    }
}

// ---------------------------------------------------------------------------
extern "C" void kernel_launch(void* const* d_in, const int* in_sizes, int n_in,
                              void* d_out, int out_size) {
    const float* enc        = (const float*)d_in[0];
    const int*   caps       = (const int*)d_in[1];
    const int*   lens       = (const int*)d_in[2];
    const float* emb        = (const float*)d_in[3];
    const float* W_enc_att  = (const float*)d_in[4];
    const float* b_enc_att  = (const float*)d_in[5];
    const float* W_dec_att  = (const float*)d_in[6];
    const float* b_dec_att  = (const float*)d_in[7];
    const float* W_full_att = (const float*)d_in[8];
    // d_in[9] = b_full_att (softmax-invariant; unused)
    const float* W_init_h   = (const float*)d_in[10];
    const float* b_init_h   = (const float*)d_in[11];
    const float* W_init_c   = (const float*)d_in[12];
    const float* b_init_c   = (const float*)d_in[13];
    const float* W_f_beta   = (const float*)d_in[14];
    const float* b_f_beta   = (const float*)d_in[15];
    const float* W_ih       = (const float*)d_in[16];
    const float* b_ih       = (const float*)d_in[17];
    const float* W_hh       = (const float*)d_in[18];
    const float* b_hh       = (const float*)d_in[19];
    const float* W_fc       = (const float*)d_in[20];
    const float* b_fc       = (const float*)d_in[21];
    float* out = (float*)d_out;

    float *ph, *pc, *pmean, *patt1, *phproj, *px, *pWcat1, *pbcat1, *pWcat2, *pembW,
          *pWfc, *pbfc, *pgpart;
    cudaGetSymbolAddress((void**)&ph,     g_h);
    cudaGetSymbolAddress((void**)&pc,     g_c);
    cudaGetSymbolAddress((void**)&pmean,  g_mean);
    cudaGetSymbolAddress((void**)&patt1,  g_att1);
    cudaGetSymbolAddress((void**)&phproj, g_hproj);
    cudaGetSymbolAddress((void**)&px,     g_x);
    cudaGetSymbolAddress((void**)&pWcat1, g_Wcat1);
    cudaGetSymbolAddress((void**)&pbcat1, g_bcat1);
    cudaGetSymbolAddress((void**)&pWcat2, g_Wcat2);
    cudaGetSymbolAddress((void**)&pembW,  g_embW);
    cudaGetSymbolAddress((void**)&pWfc,   g_Wfc);
    cudaGetSymbolAddress((void**)&pbfc,   g_bfc);
    cudaGetSymbolAddress((void**)&pgpart, g_gpart);

    // ---- precompute: 3 launches ----
    prep_misc<<<PM_GRID, 256>>>(enc, pmean, W_dec_att, W_f_beta, b_dec_att, b_f_beta,
                                pWcat1, pbcat1, W_ih, W_hh, pWcat2,
                                W_fc, b_fc, pWfc, pbfc);
    embw_kernel<<<dim3(N2_ / 256, (V_ + 7) / 8), 256>>>(emb, W_ih, b_ih, b_hh, pembW);
    gemm_combo<<<64 + 1600, 256>>>(pmean, W_init_h, b_init_h, ph,
                                   W_init_c, b_init_c, pc,
                                   enc, W_enc_att, b_enc_att, patt1);

    // ---- timestep loop: 4 launches/step ----
    for (int t = 0; t < T_; t++) {
        hproj_preds<<<HPP_GRID, 256>>>(ph, pWcat1, pbcat1, phproj, pWfc, pbfc, out, lens, t);
        attn_fused<<<B_, 512>>>(enc, patt1, W_full_att, phproj, ph, px, lens, t);
        gates_partial<<<dim3(N2_ / 128, B_ / 32, KCH_), 256>>>(px, pWcat2, pgpart, lens, t);
        lstm_cell<<<(B_ * DEC_) / 256, 256>>>(pgpart, pembW, caps, ph, pc, lens, t);
    }
    // final preds flush (t = T-1)
    preds_gemm<<<PR_BLOCKS, 256>>>(ph, pWfc, pbfc, out, lens, T_ - 1);
}

// round 15
// speedup vs baseline: 1.5067x; 1.0022x over previous
#include <cuda_runtime.h>
#include <math.h>
#include <mma.h>

using namespace nvcuda;

// Problem constants
#define B_    256
#define P_    100
#define ENC_  1536
#define DEC_  512
#define ATT_  256
#define EMB_  256
#define V_    193
#define VP_   256    // padded vocab for preds GEMM
#define T_    150
#define T1_   151
#define N1_   1792   // att2(256) + f_beta(1536)
#define K2_   2048   // awe(1536) + h(512)
#define N2_   2048   // 4*DEC gate-interleaved
#define KCH_  4      // gates split-K chunks
#define KCS_  512    // K per chunk

#define HP_BLOCKS 112            // hproj tiles
#define PR_BLOCKS 16             // preds GEMM tiles (8 M x 2 N)
#define HPP_GRID (HP_BLOCKS + PR_BLOCKS)

// Scratch (device globals: allocation-free per harness rules)
__device__ float g_h[B_ * DEC_];
__device__ float g_c[B_ * DEC_];
__device__ float g_mean[B_ * ENC_];
__device__ float g_att1[B_ * P_ * ATT_];
__device__ float g_hproj[B_ * N1_];
__device__ float g_x[B_ * K2_];          // [gated awe (1536) | h (512)]
__device__ float g_Wcat1[DEC_ * N1_];    // [W_dec_att | W_f_beta]
__device__ float g_bcat1[N1_];
__device__ float g_Wcat2[K2_ * N2_];     // rows: [W_ih_enc ; W_hh], cols interleaved d*4+g
__device__ float g_embW[V_ * N2_];       // emb@W_ih_emb + b_ih + b_hh, cols interleaved
__device__ float g_Wfc[DEC_ * VP_];      // W_fc padded to 256 cols
__device__ float g_bfc[VP_];             // b_fc padded
__device__ float g_gpart[KCH_ * B_ * N2_];  // gates split-K partials (8 MB)

__device__ __forceinline__ float sigmoidf_(float x) { return 1.0f / (1.0f + expf(-x)); }

__device__ __forceinline__ float tf32r(float x) {
    unsigned int u = __float_as_uint(x), v;
    asm("cvt.rna.tf32.f32 %0, %1;" : "=r"(v) : "r"(u));
    return __uint_as_float(v);
}
__device__ __forceinline__ float4 tf32r4(float4 v) {
    return make_float4(tf32r(v.x), tf32r(v.y), tf32r(v.z), tf32r(v.w));
}

typedef wmma::fragment<wmma::matrix_a, 16, 16, 8, wmma::precision::tf32, wmma::row_major> FragA;
typedef wmma::fragment<wmma::matrix_b, 16, 16, 8, wmma::precision::tf32, wmma::row_major> FragB;
typedef wmma::fragment<wmma::accumulator, 16, 16, 8, float> FragC;

// ---------------------------------------------------------------------------
// tf32 tensor-core 32x128 GEMM tile, BK=32, 256 threads = 8 warps (2 M x 4 N).
// Single-buffered (proven).
// ---------------------------------------------------------------------------
__device__ __forceinline__ void gemm_tc_tile(const float* __restrict__ A, int lda,
                                             const float* __restrict__ W, int N, int K,
                                             int rows0, int cols0,
                                             float (*As)[36], float (*Bs)[136],
                                             FragC& acc0, FragC& acc1,
                                             int warpM, int warpN) {
    const int tid  = threadIdx.x;
    const int arow = tid >> 3;           // 0..31
    const int acol = (tid & 7) << 2;     // 0..28
    const int brow = tid >> 5;           // 0..7 (+8r)
    const int bcol = (tid & 31) << 2;    // 0..124

    float4 aReg = *(const float4*)(A + (size_t)(rows0 + arow) * lda + acol);
    float4 bReg[4];
#pragma unroll
    for (int r = 0; r < 4; r++)
        bReg[r] = *(const float4*)(W + (size_t)(brow + 8 * r) * N + cols0 + bcol);

    for (int k0 = 0; k0 < K; k0 += 32) {
        *(float4*)&As[arow][acol] = tf32r4(aReg);
#pragma unroll
        for (int r = 0; r < 4; r++)
            *(float4*)&Bs[brow + 8 * r][bcol] = tf32r4(bReg[r]);
        __syncthreads();
        if (k0 + 32 < K) {
            aReg = *(const float4*)(A + (size_t)(rows0 + arow) * lda + k0 + 32 + acol);
#pragma unroll
            for (int r = 0; r < 4; r++)
                bReg[r] = *(const float4*)(W + (size_t)(k0 + 32 + brow + 8 * r) * N + cols0 + bcol);
        }
#pragma unroll
        for (int ks = 0; ks < 4; ks++) {
            FragA af;
            FragB bf0, bf1;
            wmma::load_matrix_sync(af, &As[warpM * 16][ks * 8], 36);
            wmma::load_matrix_sync(bf0, &Bs[ks * 8][warpN * 32], 136);
            wmma::load_matrix_sync(bf1, &Bs[ks * 8][warpN * 32 + 16], 136);
            wmma::mma_sync(acc0, af, bf0, acc0);
            wmma::mma_sync(acc1, af, bf1, acc1);
        }
        __syncthreads();
    }
}

// ---------------------------------------------------------------------------
// preds GEMM tile: out[b, tp, :] = active ? h @ Wfc_pad + bfc_pad : 0.
// ---------------------------------------------------------------------------
__device__ __forceinline__ void preds_tile(const float* __restrict__ h,
                                           const float* __restrict__ Wfc,
                                           const float* __restrict__ bfc,
                                           float* __restrict__ out,
                                           const int* __restrict__ len, int tp,
                                           int rows0, int cols0,
                                           float (*As)[36], float (*Bs)[136]) {
    const int tid = threadIdx.x;
    const int r = tid >> 3;            // 0..31
    const int cb = (tid & 7) << 4;     // 0..112
    const int b = rows0 + r;
    float* o = out + ((size_t)b * T_ + tp) * V_;

    if (tp >= len[rows0] - 1) {
#pragma unroll
        for (int u = 0; u < 16; u++) {
            const int col = cols0 + cb + u;
            if (col < V_) o[col] = 0.0f;
        }
        return;
    }

    const int warp = tid >> 5;
    const int warpM = warp >> 2, warpN = warp & 3;
    FragC acc0, acc1;
    wmma::fill_fragment(acc0, 0.0f);
    wmma::fill_fragment(acc1, 0.0f);
    gemm_tc_tile(h, DEC_, Wfc, VP_, DEC_, rows0, cols0, As, Bs, acc0, acc1, warpM, warpN);
    wmma::store_matrix_sync(&Bs[warpM * 16][warpN * 32], acc0, 136, wmma::mem_row_major);
    wmma::store_matrix_sync(&Bs[warpM * 16][warpN * 32 + 16], acc1, 136, wmma::mem_row_major);
    __syncthreads();

    const bool act = (tp < len[b] - 1);
#pragma unroll
    for (int u = 0; u < 16; u++) {
        const int col = cols0 + cb + u;
        if (col < V_) o[col] = act ? (Bs[r][cb + u] + bfc[col]) : 0.0f;
    }
}

// ---------------------------------------------------------------------------
// Fused kernel 1: blocks 0..111 hproj tiles; blocks 112..127 preds tiles (t-1).
// ---------------------------------------------------------------------------
__global__ void __launch_bounds__(256)
hproj_preds(const float* __restrict__ h, const float* __restrict__ Wcat1,
            const float* __restrict__ bcat1, float* __restrict__ hproj,
            const float* __restrict__ Wfc, const float* __restrict__ bfc,
            float* __restrict__ out, const int* __restrict__ len, int t) {
    __shared__ __align__(16) float As[32][36];
    __shared__ __align__(16) float Bs[32][136];

    const int blk = blockIdx.x;
    const int tid = threadIdx.x;

    if (blk < HP_BLOCKS) {
        const int rows0 = (blk / 14) * 32;
        const int cols0 = (blk % 14) * 128;
        if (t >= len[rows0] - 1) return;
        const int warp = tid >> 5;
        const int warpM = warp >> 2, warpN = warp & 3;
        FragC acc0, acc1;
        wmma::fill_fragment(acc0, 0.0f);
        wmma::fill_fragment(acc1, 0.0f);
        gemm_tc_tile(h, DEC_, Wcat1, N1_, DEC_, rows0, cols0, As, Bs,
                     acc0, acc1, warpM, warpN);
        wmma::store_matrix_sync(&Bs[warpM * 16][warpN * 32], acc0, 136, wmma::mem_row_major);
        wmma::store_matrix_sync(&Bs[warpM * 16][warpN * 32 + 16], acc1, 136, wmma::mem_row_major);
        __syncthreads();
        const int r = tid >> 3;
        const int cb = (tid & 7) << 4;
#pragma unroll
        for (int u = 0; u < 4; u++) {
            const int col = cb + u * 4;
            float4 v = *(const float4*)&Bs[r][col];
            float4 bv = *(const float4*)(bcat1 + cols0 + col);
            v.x += bv.x; v.y += bv.y; v.z += bv.z; v.w += bv.w;
            *(float4*)(hproj + (size_t)(rows0 + r) * N1_ + cols0 + col) = v;
        }
    } else {
        if (t == 0) return;
        const int pblk = blk - HP_BLOCKS;           // 0..15
        const int rows0 = (pblk & 7) * 32;
        const int cols0 = (pblk >> 3) * 128;
        preds_tile(h, Wfc, bfc, out, len, t - 1, rows0, cols0, As, Bs);
    }
}

// Final preds flush for tp = T-1 (16 blocks).
__global__ void __launch_bounds__(256)
preds_gemm(const float* __restrict__ h, const float* __restrict__ Wfc,
           const float* __restrict__ bfc, float* __restrict__ out,
           const int* __restrict__ len, int tp) {
    __shared__ __align__(16) float As[32][36];
    __shared__ __align__(16) float Bs[32][136];
    const int pblk = blockIdx.x;
    const int rows0 = (pblk & 7) * 32;
    const int cols0 = (pblk >> 3) * 128;
    preds_tile(h, Wfc, bfc, out, len, tp, rows0, cols0, As, Bs);
}

// ---------------------------------------------------------------------------
// Fused attention: one block (512 threads) per batch element.
// ---------------------------------------------------------------------------
__global__ void __launch_bounds__(512)
attn_fused(const float* __restrict__ enc, const float* __restrict__ att1,
           const float* __restrict__ Wfull, const float* __restrict__ hproj,
           const float* __restrict__ h, float* __restrict__ x,
           const int* __restrict__ len, int t) {
    const int b = blockIdx.x;
    if (t >= len[b] - 1) return;
    const int tid = threadIdx.x;
    const int warp = tid >> 5, lane = tid & 31;

    __shared__ float att2s[ATT_];
    __shared__ float wf[ATT_];
    __shared__ float es[P_ + 4];

    if (tid < ATT_) {
        att2s[tid] = hproj[(size_t)b * N1_ + tid];
        wf[tid] = Wfull[tid];
    }
    __syncthreads();

    for (int p = warp; p < P_; p += 16) {
        const float* a1 = att1 + ((size_t)(b * P_ + p)) * ATT_;
        float part = 0.0f;
#pragma unroll 4
        for (int j = lane; j < ATT_; j += 32)
            part += fmaxf(a1[j] + att2s[j], 0.0f) * wf[j];
#pragma unroll
        for (int o = 16; o; o >>= 1) part += __shfl_xor_sync(0xffffffffu, part, o);
        if (lane == 0) es[p] = part;
    }
    __syncthreads();

    if (tid < 32) {
        float m = -1e30f;
        for (int p = tid; p < P_; p += 32) m = fmaxf(m, es[p]);
#pragma unroll
        for (int o = 16; o; o >>= 1) m = fmaxf(m, __shfl_xor_sync(0xffffffffu, m, o));
        float s = 0.0f;
        for (int p = tid; p < P_; p += 32) {
            float ex = expf(es[p] - m);
            es[p] = ex;
            s += ex;
        }
#pragma unroll
        for (int o = 16; o; o >>= 1) s += __shfl_xor_sync(0xffffffffu, s, o);
        float inv = 1.0f / s;
        for (int p = tid; p < P_; p += 32) es[p] *= inv;
    }
    __syncthreads();

    x[(size_t)b * K2_ + 1536 + tid] = h[(size_t)b * DEC_ + tid];

    if (tid < ENC_ / 4) {
        const float4* ep = (const float4*)(enc + ((size_t)b * P_) * ENC_);
        float4 acc = make_float4(0.f, 0.f, 0.f, 0.f);
#pragma unroll 4
        for (int p = 0; p < P_; p++) {
            float4 v = ep[(size_t)p * (ENC_ / 4) + tid];
            float a = es[p];
            acc.x += a * v.x; acc.y += a * v.y; acc.z += a * v.z; acc.w += a * v.w;
        }
        const int col = tid * 4;
        float4 gl = *(const float4*)(hproj + (size_t)b * N1_ + ATT_ + col);
        float4 o;
        o.x = acc.x * sigmoidf_(gl.x);
        o.y = acc.y * sigmoidf_(gl.y);
        o.z = acc.z * sigmoidf_(gl.z);
        o.w = acc.w * sigmoidf_(gl.w);
        *(float4*)(x + (size_t)b * K2_ + col) = o;
    }
}

// ---------------------------------------------------------------------------
// gates split-K partial GEMM: grid (16 cols, 8 rows, 4 K-chunks).
// Writes raw partials (no bias) to gpart[chunk][b][cp].
// ---------------------------------------------------------------------------
__global__ void __launch_bounds__(256)
gates_partial(const float* __restrict__ x, const float* __restrict__ W,
              float* __restrict__ gpart, const int* __restrict__ len, int t) {
    __shared__ __align__(16) float As[32][36];
    __shared__ __align__(16) float Bs[32][136];
    const int rows0 = blockIdx.y * 32;
    if (t >= len[rows0] - 1) return;
    const int cols0 = blockIdx.x * 128;
    const int kc = blockIdx.z;
    const int warp = threadIdx.x >> 5;
    const int warpM = warp >> 2, warpN = warp & 3;

    FragC acc0, acc1;
    wmma::fill_fragment(acc0, 0.0f);
    wmma::fill_fragment(acc1, 0.0f);
    gemm_tc_tile(x + kc * KCS_, K2_, W + (size_t)(kc * KCS_) * N2_, N2_, KCS_,
                 rows0, cols0, As, Bs, acc0, acc1, warpM, warpN);

    wmma::store_matrix_sync(&Bs[warpM * 16][warpN * 32], acc0, 136, wmma::mem_row_major);
    wmma::store_matrix_sync(&Bs[warpM * 16][warpN * 32 + 16], acc1, 136, wmma::mem_row_major);
    __syncthreads();

    const int tid = threadIdx.x;
    const int r = tid >> 3;
    const int cb = (tid & 7) << 4;
    float* gp = gpart + ((size_t)kc * B_ + (rows0 + r)) * N2_ + cols0;
#pragma unroll
    for (int u = 0; u < 4; u++) {
        *(float4*)(gp + cb + u * 4) = *(const float4*)&Bs[r][cb + u * 4];
    }
}

// ---------------------------------------------------------------------------
// LSTM cell epilogue: sum 4 chunk partials + embW[token], apply cell update.
// One thread per (b, d). Deterministic chunk-sum order.
// ---------------------------------------------------------------------------
__global__ void __launch_bounds__(256)
lstm_cell(const float* __restrict__ gpart, const float* __restrict__ embW,
          const int* __restrict__ caps, float* __restrict__ h, float* __restrict__ c,
          const int* __restrict__ len, int t) {
    const int idx = blockIdx.x * 256 + threadIdx.x;   // 0 .. B_*DEC_-1
    const int b = idx >> 9;
    const int d = idx & (DEC_ - 1);
    if (t >= len[b] - 1) return;
    const int token = caps[b * T1_ + t];

    const float4* gp = (const float4*)gpart;
    const size_t base = (size_t)b * (N2_ / 4) + d;
    float4 s0 = gp[base];
    float4 s1 = gp[(size_t)1 * B_ * (N2_ / 4) + base];
    float4 s2 = gp[(size_t)2 * B_ * (N2_ / 4) + base];
    float4 s3 = gp[(size_t)3 * B_ * (N2_ / 4) + base];
    float4 ew = *(const float4*)(embW + (size_t)token * N2_ + d * 4);

    float vi = ((s0.x + s1.x) + (s2.x + s3.x)) + ew.x;
    float vf = ((s0.y + s1.y) + (s2.y + s3.y)) + ew.y;
    float vg = ((s0.z + s1.z) + (s2.z + s3.z)) + ew.z;
    float vo = ((s0.w + s1.w) + (s2.w + s3.w)) + ew.w;

    float c_old = c[(size_t)b * DEC_ + d];
    float ii = sigmoidf_(vi);
    float ff = sigmoidf_(vf);
    float gg = tanhf(vg);
    float oo = sigmoidf_(vo);
    float cn = ff * c_old + ii * gg;
    float hn = oo * tanhf(cn);
    c[(size_t)b * DEC_ + d] = cn;
    h[(size_t)b * DEC_ + d] = hn;
}

// ---------------------------------------------------------------------------
// Merged precompute GEMMs: blocks 0..31 h0, 32..63 c0, 64..1663 att1.
// ---------------------------------------------------------------------------
__global__ void __launch_bounds__(256)
gemm_combo(const float* __restrict__ mean,
           const float* __restrict__ W_init_h, const float* __restrict__ b_init_h,
           float* __restrict__ h,
           const float* __restrict__ W_init_c, const float* __restrict__ b_init_c,
           float* __restrict__ c,
           const float* __restrict__ enc,
           const float* __restrict__ W_enc_att, const float* __restrict__ b_enc_att,
           float* __restrict__ att1) {
    __shared__ __align__(16) float As[32][36];
    __shared__ __align__(16) float Bs[32][136];
    const int blk = blockIdx.x;
    const float* A;
    const float* W;
    const float* bias;
    float* C;
    int N, rows0, cols0;
    if (blk < 32) {
        A = mean; W = W_init_h; bias = b_init_h; C = h; N = DEC_;
        rows0 = (blk & 7) * 32; cols0 = (blk >> 3) * 128;
    } else if (blk < 64) {
        A = mean; W = W_init_c; bias = b_init_c; C = c; N = DEC_;
        rows0 = ((blk - 32) & 7) * 32; cols0 = ((blk - 32) >> 3) * 128;
    } else {
        const int u = blk - 64;           // 0..1599
        A = enc; W = W_enc_att; bias = b_enc_att; C = att1; N = ATT_;
        rows0 = (u % 800) * 32; cols0 = (u / 800) * 128;
    }
    const int warp = threadIdx.x >> 5;
    const int warpM = warp >> 2, warpN = warp & 3;
    FragC acc0, acc1;
    wmma::fill_fragment(acc0, 0.0f);
    wmma::fill_fragment(acc1, 0.0f);
    gemm_tc_tile(A, ENC_, W, N, ENC_, rows0, cols0, As, Bs, acc0, acc1, warpM, warpN);

    wmma::store_matrix_sync(&Bs[warpM * 16][warpN * 32], acc0, 136, wmma::mem_row_major);
    wmma::store_matrix_sync(&Bs[warpM * 16][warpN * 32 + 16], acc1, 136, wmma::mem_row_major);
    __syncthreads();

    const int tid = threadIdx.x;
    const int r = tid >> 3;
    const int cb = (tid & 7) << 4;
#pragma unroll
    for (int u = 0; u < 4; u++) {
        const int col = cb + u * 4;
        float4 v = *(const float4*)&Bs[r][col];
        float4 bv = *(const float4*)(bias + cols0 + col);
        v.x += bv.x; v.y += bv.y; v.z += bv.z; v.w += bv.w;
        *(float4*)(C + (size_t)(rows0 + r) * N + cols0 + col) = v;
    }
}

// ---------------------------------------------------------------------------
// Merged misc precompute: mean | wcat1 | wcat2 | Wfc pad.
// ---------------------------------------------------------------------------
#define PM_MEAN  1536
#define PM_WCAT1 3584
#define PM_WCAT2 16384
#define PM_WFC   512
#define PM_GRID  (PM_MEAN + PM_WCAT1 + PM_WCAT2 + PM_WFC)
__global__ void prep_misc(const float* __restrict__ enc, float* __restrict__ mean,
                          const float* __restrict__ Wda, const float* __restrict__ Wfb,
                          const float* __restrict__ bda, const float* __restrict__ bfb,
                          float* __restrict__ Wc1, float* __restrict__ bc1,
                          const float* __restrict__ Wih, const float* __restrict__ Whh,
                          float* __restrict__ Wc2,
                          const float* __restrict__ Wfc, const float* __restrict__ bfc,
                          float* __restrict__ Wfcp, float* __restrict__ bfcp) {
    const int blk = blockIdx.x;
    const int tid = threadIdx.x;
    if (blk < PM_MEAN) {
        const int b = blk / 6;
        const int e = (blk % 6) * 256 + tid;
        const float* ep = enc + ((size_t)b * P_) * ENC_ + e;
        float s = 0.0f;
#pragma unroll 4
        for (int p = 0; p < P_; p++) s += ep[(size_t)p * ENC_];
        mean[(size_t)b * ENC_ + e] = s * (1.0f / P_);
    } else if (blk < PM_MEAN + PM_WCAT1) {
        const int idx = (blk - PM_MEAN) * 256 + tid;     // < DEC_*N1_
        const int k = idx / N1_, n = idx % N1_;
        Wc1[idx] = (n < ATT_) ? Wda[k * ATT_ + n] : Wfb[k * ENC_ + (n - ATT_)];
        if (k == 0) bc1[n] = (n < ATT_) ? bda[n] : bfb[n - ATT_];
    } else if (blk < PM_MEAN + PM_WCAT1 + PM_WCAT2) {
        const int idx = (blk - PM_MEAN - PM_WCAT1) * 256 + tid;   // < K2_*N2_
        const int k = idx / N2_, cp = idx % N2_;
        const int dd = cp >> 2, g = cp & 3;
        const int oc = g * DEC_ + dd;
        Wc2[idx] = (k < 1536) ? Wih[(size_t)(256 + k) * N2_ + oc]
                              : Whh[(size_t)(k - 1536) * N2_ + oc];
    } else {
        const int idx = (blk - PM_MEAN - PM_WCAT1 - PM_WCAT2) * 256 + tid;  // < DEC_*VP_
        const int k = idx / VP_, n = idx % VP_;
        Wfcp[idx] = (n < V_) ? Wfc[k * V_ + n] : 0.0f;
        if (k == 0) bfcp[n] = (n < V_) ? bfc[n] : 0.0f;
    }
}

// embW[v, d*4+g] = sum_k emb[v,k] * W_ih[k, g*512+d] + b_ih + b_hh
__global__ void embw_kernel(const float* __restrict__ emb, const float* __restrict__ Wih,
                            const float* __restrict__ bih, const float* __restrict__ bhh,
                            float* __restrict__ out) {
    const int oc = blockIdx.x * 256 + threadIdx.x;   // 0..2047
    const int v0 = blockIdx.y * 8;
    __shared__ float er[8][EMB_];
#pragma unroll
    for (int r = 0; r < 8; r++) {
        int v = v0 + r;
        er[r][threadIdx.x] = (v < V_) ? emb[(size_t)v * EMB_ + threadIdx.x] : 0.0f;
    }
    __syncthreads();
    float base = bih[oc] + bhh[oc];
    float acc[8];
#pragma unroll
    for (int r = 0; r < 8; r++) acc[r] = base;
    for (int k = 0; k < EMB_; k++) {
        float w = Wih[(size_t)k * N2_ + oc];
#pragma unroll
        for (int r = 0; r < 8; r++) acc[r] += er[r][k] * w;
    }
    const int dd = oc & (DEC_ - 1);
    const int g = oc >> 9;
#pragma unroll
    for (int r = 0; r < 8; r++) {
        int v = v0 + r;
        if (v < V_) out[(size_t)v * N2_ + dd * 4 + g] = acc[r];
    }
}

// ---------------------------------------------------------------------------
extern "C" void kernel_launch(void* const* d_in, const int* in_sizes, int n_in,
                              void* d_out, int out_size) {
    const float* enc        = (const float*)d_in[0];
    const int*   caps       = (const int*)d_in[1];
    const int*   lens       = (const int*)d_in[2];
    const float* emb        = (const float*)d_in[3];
    const float* W_enc_att  = (const float*)d_in[4];
    const float* b_enc_att  = (const float*)d_in[5];
    const float* W_dec_att  = (const float*)d_in[6];
    const float* b_dec_att  = (const float*)d_in[7];
    const float* W_full_att = (const float*)d_in[8];
    // d_in[9] = b_full_att (softmax-invariant; unused)
    const float* W_init_h   = (const float*)d_in[10];
    const float* b_init_h   = (const float*)d_in[11];
    const float* W_init_c   = (const float*)d_in[12];
    const float* b_init_c   = (const float*)d_in[13];
    const float* W_f_beta   = (const float*)d_in[14];
    const float* b_f_beta   = (const float*)d_in[15];
    const float* W_ih       = (const float*)d_in[16];
    const float* b_ih       = (const float*)d_in[17];
    const float* W_hh       = (const float*)d_in[18];
    const float* b_hh       = (const float*)d_in[19];
    const float* W_fc       = (const float*)d_in[20];
    const float* b_fc       = (const float*)d_in[21];
    float* out = (float*)d_out;

    float *ph, *pc, *pmean, *patt1, *phproj, *px, *pWcat1, *pbcat1, *pWcat2, *pembW,
          *pWfc, *pbfc, *pgpart;
    cudaGetSymbolAddress((void**)&ph,     g_h);
    cudaGetSymbolAddress((void**)&pc,     g_c);
    cudaGetSymbolAddress((void**)&pmean,  g_mean);
    cudaGetSymbolAddress((void**)&patt1,  g_att1);
    cudaGetSymbolAddress((void**)&phproj, g_hproj);
    cudaGetSymbolAddress((void**)&px,     g_x);
    cudaGetSymbolAddress((void**)&pWcat1, g_Wcat1);
    cudaGetSymbolAddress((void**)&pbcat1, g_bcat1);
    cudaGetSymbolAddress((void**)&pWcat2, g_Wcat2);
    cudaGetSymbolAddress((void**)&pembW,  g_embW);
    cudaGetSymbolAddress((void**)&pWfc,   g_Wfc);
    cudaGetSymbolAddress((void**)&pbfc,   g_bfc);
    cudaGetSymbolAddress((void**)&pgpart, g_gpart);

    // ---- precompute: 3 launches ----
    prep_misc<<<PM_GRID, 256>>>(enc, pmean, W_dec_att, W_f_beta, b_dec_att, b_f_beta,
                                pWcat1, pbcat1, W_ih, W_hh, pWcat2,
                                W_fc, b_fc, pWfc, pbfc);
    embw_kernel<<<dim3(N2_ / 256, (V_ + 7) / 8), 256>>>(emb, W_ih, b_ih, b_hh, pembW);
    gemm_combo<<<64 + 1600, 256>>>(pmean, W_init_h, b_init_h, ph,
                                   W_init_c, b_init_c, pc,
                                   enc, W_enc_att, b_enc_att, patt1);

    // ---- timestep loop: 4 launches/step ----
    for (int t = 0; t < T_; t++) {
        hproj_preds<<<HPP_GRID, 256>>>(ph, pWcat1, pbcat1, phproj, pWfc, pbfc, out, lens, t);
        attn_fused<<<B_, 512>>>(enc, patt1, W_full_att, phproj, ph, px, lens, t);
        gates_partial<<<dim3(N2_ / 128, B_ / 32, KCH_), 256>>>(px, pWcat2, pgpart, lens, t);
        lstm_cell<<<(B_ * DEC_) / 256, 256>>>(pgpart, pembW, caps, ph, pc, lens, t);
    }
    // final preds flush (t = T-1)
    preds_gemm<<<PR_BLOCKS, 256>>>(ph, pWfc, pbfc, out, lens, T_ - 1);
}